// round 10
// baseline (speedup 1.0000x reference)
#include <cuda_runtime.h>
#include <cuda_fp16.h>
#include <math.h>
#include <stdint.h>

#define N_SEQ  4096
#define SIZE_K 8192
#define HALF_K 4096

#define BM   128
#define BN   128
#define GT   256         // threads per GEMM CTA (8 warps)

#define LSCALE 2048.0f          // 2^11: fp16 lo-part pre-scale (scores path)
#define INVC   (1.0f / 2048.0f)

// fp8 scales (proj cross): products land at 2^27
#define SXH  32.0f              // 2^5   x -> fp8
#define SXL  65536.0f           // 2^16  (x - h16(x)) -> fp8
#define SWH  2048.0f            // 2^11  W -> fp8
#define SWL  4194304.0f         // 2^22  (W - h16(W)) -> fp8
#define INV_CROSS (1.0f / 134217728.0f)  // 2^-27

// ---------------- scratch (static device globals; no runtime alloc) ----------
__device__ __half   g_xh[(size_t)N_SEQ * SIZE_K];          // fp16(x)
__device__ uint8_t  g_xh8[(size_t)N_SEQ * SIZE_K];         // e4m3(x * 2^5)
__device__ uint8_t  g_xl8[(size_t)N_SEQ * SIZE_K];         // e4m3((x-h) * 2^16)
__device__ __half   g_wkh[(size_t)HALF_K * SIZE_K];        // fp16(Wk^T)
__device__ uint8_t  g_wkh8[(size_t)HALF_K * SIZE_K];       // e4m3(W * 2^11)
__device__ uint8_t  g_wkl8[(size_t)HALF_K * SIZE_K];       // e4m3((W-h) * 2^22)
__device__ __half   g_wvh[(size_t)HALF_K * SIZE_K];
__device__ uint8_t  g_wvh8[(size_t)HALF_K * SIZE_K];
__device__ uint8_t  g_wvl8[(size_t)HALF_K * SIZE_K];
__device__ __half   g_kh[(size_t)N_SEQ * HALF_K];          // K hi (fp16)
__device__ __half   g_kl[(size_t)N_SEQ * HALF_K];          // K lo * 2^11
__device__ __half   g_vh[(size_t)N_SEQ * HALF_K];          // V hi
__device__ __half   g_vl[(size_t)N_SEQ * HALF_K];          // V lo * 2^11
__device__ float    g_v [(size_t)N_SEQ * HALF_K];          // V fp32
__device__ float    g_s [(size_t)N_SEQ * N_SEQ];           // scores fp32

// ---------------- PTX helpers (base sm_103 features only) --------------------
static __device__ __forceinline__ uint32_t smem_u32(const void* p) {
    uint32_t a;
    asm("{ .reg .u64 t; cvta.to.shared.u64 t, %1; cvt.u32.u64 %0, t; }" : "=r"(a) : "l"(p));
    return a;
}
static __device__ __forceinline__ void cp16(uint32_t s, const void* g) {
    asm volatile("cp.async.cg.shared.global [%0], [%1], 16;" :: "r"(s), "l"(g));
}
static __device__ __forceinline__ void cp_commit() {
    asm volatile("cp.async.commit_group;" ::: "memory");
}
template<int NP> static __device__ __forceinline__ void cp_wait() {
    asm volatile("cp.async.wait_group %0;" :: "n"(NP) : "memory");
}
static __device__ __forceinline__ void ldsm4(uint32_t* r, uint32_t addr) {
    asm volatile("ldmatrix.sync.aligned.m8n8.x4.shared.b16 {%0,%1,%2,%3}, [%4];"
        : "=r"(r[0]), "=r"(r[1]), "=r"(r[2]), "=r"(r[3]) : "r"(addr));
}
static __device__ __forceinline__ void mma16816_f32(float* c, const uint32_t* a, const uint32_t* b) {
    asm volatile(
        "mma.sync.aligned.m16n8k16.row.col.f32.f16.f16.f32 "
        "{%0,%1,%2,%3}, {%4,%5,%6,%7}, {%8,%9}, {%0,%1,%2,%3};"
        : "+f"(c[0]), "+f"(c[1]), "+f"(c[2]), "+f"(c[3])
        : "r"(a[0]), "r"(a[1]), "r"(a[2]), "r"(a[3]), "r"(b[0]), "r"(b[1]));
}
static __device__ __forceinline__ void mma16816_f16(uint32_t* c, const uint32_t* a, const uint32_t* b) {
    asm volatile(
        "mma.sync.aligned.m16n8k16.row.col.f16.f16.f16.f16 "
        "{%0,%1}, {%2,%3,%4,%5}, {%6,%7}, {%0,%1};"
        : "+r"(c[0]), "+r"(c[1])
        : "r"(a[0]), "r"(a[1]), "r"(a[2]), "r"(a[3]), "r"(b[0]), "r"(b[1]));
}
static __device__ __forceinline__ void mma16832_e4m3(float* c, const uint32_t* a, const uint32_t* b) {
    asm volatile(
        "mma.sync.aligned.m16n8k32.row.col.f32.e4m3.e4m3.f32 "
        "{%0,%1,%2,%3}, {%4,%5,%6,%7}, {%8,%9}, {%0,%1,%2,%3};"
        : "+f"(c[0]), "+f"(c[1]), "+f"(c[2]), "+f"(c[3])
        : "r"(a[0]), "r"(a[1]), "r"(a[2]), "r"(a[3]), "r"(b[0]), "r"(b[1]));
}
// .b16 dest: low byte = cvt(lo), high byte = cvt(hi)
static __device__ __forceinline__ uint16_t e4m3x2(float hi, float lo) {
    uint16_t r;
    asm("cvt.rn.satfinite.e4m3x2.f32 %0, %1, %2;" : "=h"(r) : "f"(hi), "f"(lo));
    return r;
}
static __device__ __forceinline__ uint32_t pack4_e4m3(float e0, float e1, float e2, float e3) {
    return (uint32_t)e4m3x2(e1, e0) | ((uint32_t)e4m3x2(e3, e2) << 16);
}
static __device__ __forceinline__ void split2h(float x0, float x1, uint32_t& h, uint32_t& l) {
    __half h0 = __float2half_rn(x0), h1 = __float2half_rn(x1);
    __half l0 = __float2half_rn((x0 - __half2float(h0)) * LSCALE);
    __half l1 = __float2half_rn((x1 - __half2float(h1)) * LSCALE);
    h = (uint32_t)__half_as_ushort(h0) | ((uint32_t)__half_as_ushort(h1) << 16);
    l = (uint32_t)__half_as_ushort(l0) | ((uint32_t)__half_as_ushort(l1) << 16);
}

// ---------------- convert / split kernels ------------------------------------
__global__ __launch_bounds__(256)
void convert_x_kernel(const float* __restrict__ x)
{
    const size_t total4 = (size_t)N_SEQ * SIZE_K / 4;
    uint32_t* xh2  = reinterpret_cast<uint32_t*>(g_xh);
    uint32_t* xh8w = reinterpret_cast<uint32_t*>(g_xh8);
    uint32_t* xl8w = reinterpret_cast<uint32_t*>(g_xl8);
    for (size_t i = (size_t)blockIdx.x * blockDim.x + threadIdx.x; i < total4;
         i += (size_t)gridDim.x * blockDim.x) {
        float4 v = reinterpret_cast<const float4*>(x)[i];
        __half h0 = __float2half_rn(v.x), h1 = __float2half_rn(v.y);
        __half h2 = __float2half_rn(v.z), h3 = __float2half_rn(v.w);
        float l0 = v.x - __half2float(h0);
        float l1 = v.y - __half2float(h1);
        float l2 = v.z - __half2float(h2);
        float l3 = v.w - __half2float(h3);
        xh2[2*i]   = (uint32_t)__half_as_ushort(h0) | ((uint32_t)__half_as_ushort(h1) << 16);
        xh2[2*i+1] = (uint32_t)__half_as_ushort(h2) | ((uint32_t)__half_as_ushort(h3) << 16);
        xh8w[i] = pack4_e4m3(v.x * SXH, v.y * SXH, v.z * SXH, v.w * SXH);
        xl8w[i] = pack4_e4m3(l0 * SXL, l1 * SXL, l2 * SXL, l3 * SXL);
    }
}

// W [SIZE_K, HALF_K] fp32 -> WT [HALF_K, SIZE_K]: fp16 hi + fp8 hi/lo
template<int WSEL>
__global__ __launch_bounds__(256)
void transpose_split_kernel(const float* __restrict__ W)
{
    __half*  dh  = (WSEL == 0) ? g_wkh  : g_wvh;
    uint8_t* dh8 = (WSEL == 0) ? g_wkh8 : g_wvh8;
    uint8_t* dl8 = (WSEL == 0) ? g_wkl8 : g_wvl8;
    __shared__ float t[32][33];
    int n0 = blockIdx.x * 32;
    int k0 = blockIdx.y * 32;
    int tx = threadIdx.x, ty = threadIdx.y;   // block (32, 8)
    #pragma unroll
    for (int i = 0; i < 4; i++)
        t[ty + i * 8][tx] = W[(size_t)(k0 + ty + i * 8) * HALF_K + n0 + tx];
    __syncthreads();
    #pragma unroll
    for (int i = 0; i < 4; i++) {
        int n = n0 + ty + i * 8;
        int k = k0 + tx;
        float v = t[tx][ty + i * 8];
        __half h = __float2half_rn(v);
        float l = v - __half2float(h);
        dh[(size_t)n * SIZE_K + k]  = h;
        dh8[(size_t)n * SIZE_K + k] = (uint8_t)(e4m3x2(0.0f, v * SWH) & 0xFF);
        dl8[(size_t)n * SIZE_K + k] = (uint8_t)(e4m3x2(0.0f, l * SWL) & 0xFF);
    }
}

// ---------------- projection GEMM: fp16 hh + fp8 cross terms ------------------
// MODE 0: K proj (out: g_kh/g_kl, bias=bk)   MODE 1: V proj (out: g_v,g_vh/g_vl)
// smem stage (32 KB, chunk K=32): Ah 8K | Bh 8K | Ah8 4K | Al8 4K | Bh8 4K | Bl8 4K
#define P_STG 32768u
#define P_NSTG 4
#define P_SMEM (P_NSTG * P_STG)
#define OA8  16384u
#define OAL8 20480u
#define OB8  24576u
#define OBL8 28672u
#define P_BKC 32

template<int MODE>
__global__ __launch_bounds__(GT)
void gemm_proj_kernel(const float* __restrict__ bias)
{
    const __half* Ah = g_xh;
    const uint8_t *A8 = g_xh8, *Al8 = g_xl8;
    const __half* Bh = (MODE == 0) ? g_wkh : g_wvh;
    const uint8_t *B8  = (MODE == 0) ? g_wkh8 : g_wvh8;
    const uint8_t *Bl8 = (MODE == 0) ? g_wkl8 : g_wvl8;
    const int Ktot = SIZE_K;

    extern __shared__ char smem[];
    const uint32_t sb = smem_u32(smem);
    const int tid  = threadIdx.x;
    const int wid  = tid >> 5;
    const int lane = tid & 31;
    const int wm   = wid & 3;     // warp row 0..3 (32 rows)
    const int wn   = wid >> 2;    // warp col 0..1 (64 cols)

    const int bm = blockIdx.x * BM;
    const int bn = blockIdx.y * BN;

    float acc[2][8][4];   // hh (fp16 in, fp32 acc)
    float acx[2][8][4];   // cross (fp8, scale 2^27)
    #pragma unroll
    for (int t = 0; t < 2; t++)
        #pragma unroll
        for (int n = 0; n < 8; n++)
            #pragma unroll
            for (int q = 0; q < 4; q++) { acc[t][n][q] = 0.0f; acx[t][n][q] = 0.0f; }

    const int nch = Ktot / P_BKC;

    auto load_chunk = [&](int ch) {
        const uint32_t stg = sb + (uint32_t)(ch % P_NSTG) * P_STG;
        const size_t k0 = (size_t)ch * P_BKC;
        // fp16 hi tiles: 128 rows x 64B
        #pragma unroll
        for (int i = 0; i < 2; i++) {
            int pos = tid + i * GT;            // 0..511
            int row = pos >> 2, seg = pos & 3;
            uint32_t soff = row * 64 + ((seg ^ ((row >> 1) & 3)) << 4);
            cp16(stg + soff,         Ah + (size_t)(bm + row) * Ktot + k0 + seg * 8);
            cp16(stg + 8192u + soff, Bh + (size_t)(bn + row) * Ktot + k0 + seg * 8);
        }
        // fp8 tiles: 128 rows x 32B, swizzle seg ^ ((row>>2)&1)
        {
            int row = tid >> 1, c = tid & 1;
            uint32_t soff = row * 32 + ((c ^ ((row >> 2) & 1)) << 4);
            size_t ga = (size_t)(bm + row) * Ktot + k0 + c * 16;
            size_t gb = (size_t)(bn + row) * Ktot + k0 + c * 16;
            cp16(stg + OA8  + soff, A8  + ga);
            cp16(stg + OAL8 + soff, Al8 + ga);
            cp16(stg + OB8  + soff, B8  + gb);
            cp16(stg + OBL8 + soff, Bl8 + gb);
        }
    };

    load_chunk(0); cp_commit();
    load_chunk(1); cp_commit();
    load_chunk(2); cp_commit();

    for (int ch = 0; ch < nch; ++ch) {
        cp_wait<2>();
        __syncthreads();
        if (ch + 3 < nch) load_chunk(ch + 3);
        cp_commit();

        const uint32_t stg = sb + (uint32_t)(ch % P_NSTG) * P_STG;

        // ---- fp8 cross terms (one k32 step covers the chunk)
        uint32_t ah8[2][4], al8[2][4], bh8[4][4], bl8[4][4];
        #pragma unroll
        for (int t = 0; t < 2; ++t) {
            int row = wm * 32 + t * 16 + (lane & 15);
            int kh  = lane >> 4;
            uint32_t off = row * 32 + ((kh ^ ((row >> 2) & 1)) << 4);
            ldsm4(ah8[t], stg + OA8  + off);
            ldsm4(al8[t], stg + OAL8 + off);
        }
        #pragma unroll
        for (int p = 0; p < 4; ++p) {
            int row = wn * 64 + p * 16 + ((lane >> 4) << 3) + (lane & 7);
            int kh  = (lane >> 3) & 1;
            uint32_t off = row * 32 + ((kh ^ ((row >> 2) & 1)) << 4);
            ldsm4(bh8[p], stg + OB8  + off);
            ldsm4(bl8[p], stg + OBL8 + off);
        }
        // hl: x_hi8 * w_lo8
        #pragma unroll
        for (int t = 0; t < 2; ++t)
            #pragma unroll
            for (int nt = 0; nt < 8; ++nt)
                mma16832_e4m3(acx[t][nt], ah8[t], &bl8[nt >> 1][(nt & 1) * 2]);
        // lh: x_lo8 * w_hi8
        #pragma unroll
        for (int t = 0; t < 2; ++t)
            #pragma unroll
            for (int nt = 0; nt < 8; ++nt)
                mma16832_e4m3(acx[t][nt], al8[t], &bh8[nt >> 1][(nt & 1) * 2]);

        // ---- fp16 hi*hi
        #pragma unroll
        for (int k16 = 0; k16 < 2; ++k16) {
            uint32_t afh[2][4], bfh[4][4];
            #pragma unroll
            for (int t = 0; t < 2; ++t) {
                int row = wm * 32 + t * 16 + (lane & 15);
                int seg = k16 * 2 + (lane >> 4);
                uint32_t off = row * 64 + ((seg ^ ((row >> 1) & 3)) << 4);
                ldsm4(afh[t], stg + off);
            }
            #pragma unroll
            for (int p = 0; p < 4; ++p) {
                int row = wn * 64 + p * 16 + ((lane >> 4) << 3) + (lane & 7);
                int seg = k16 * 2 + ((lane >> 3) & 1);
                uint32_t off = row * 64 + ((seg ^ ((row >> 1) & 3)) << 4);
                ldsm4(bfh[p], stg + 8192u + off);
            }
            #pragma unroll
            for (int t = 0; t < 2; ++t)
                #pragma unroll
                for (int nt = 0; nt < 8; ++nt)
                    mma16816_f32(acc[t][nt], afh[t], &bfh[nt >> 1][(nt & 1) * 2]);
        }
    }

    // ---- epilogue
    #pragma unroll
    for (int t = 0; t < 2; ++t) {
        #pragma unroll
        for (int nt = 0; nt < 8; ++nt) {
            const int n  = bn + wn * 64 + nt * 8 + (lane & 3) * 2;
            const int m0 = bm + wm * 32 + t * 16 + (lane >> 2);
            float b0 = __ldg(&bias[n]), b1 = __ldg(&bias[n + 1]);
            float x0 = acc[t][nt][0] + acx[t][nt][0] * INV_CROSS + b0;
            float x1 = acc[t][nt][1] + acx[t][nt][1] * INV_CROSS + b1;
            float y0 = acc[t][nt][2] + acx[t][nt][2] * INV_CROSS + b0;
            float y1 = acc[t][nt][3] + acx[t][nt][3] * INV_CROSS + b1;
            if (MODE == 1) {
                *(float2*)&g_v[(size_t)m0 * HALF_K + n]       = make_float2(x0, x1);
                *(float2*)&g_v[(size_t)(m0 + 8) * HALF_K + n] = make_float2(y0, y1);
            }
            __half* dsth = (MODE == 0) ? g_kh : g_vh;
            __half* dstl = (MODE == 0) ? g_kl : g_vl;
            uint32_t h, l;
            split2h(x0, x1, h, l);
            *(uint32_t*)&dsth[(size_t)m0 * HALF_K + n] = h;
            *(uint32_t*)&dstl[(size_t)m0 * HALF_K + n] = l;
            split2h(y0, y1, h, l);
            *(uint32_t*)&dsth[(size_t)(m0 + 8) * HALF_K + n] = h;
            *(uint32_t*)&dstl[(size_t)(m0 + 8) * HALF_K + n] = l;
        }
    }
}

// ---------------- scores GEMM: fp16 3-term (round-9 proven) -------------------
#define S_STG 32768u
#define S_BUF 8192u
#define S_NSTG 3
#define S_SMEM (S_NSTG * S_STG)
#define S_BKC 32

__global__ __launch_bounds__(GT, 2)
void gemm_sc_kernel()
{
    const __half *Ah = g_vh, *Al = g_vl, *Bh = g_kh, *Bl = g_kl;
    const int Ktot = HALF_K;

    extern __shared__ char smem[];
    const uint32_t sb = smem_u32(smem);
    const int tid  = threadIdx.x;
    const int wid  = tid >> 5;
    const int lane = tid & 31;
    const int wm   = wid & 3;
    const int wn   = wid >> 2;

    const int bm = blockIdx.x * BM;
    const int bn = blockIdx.y * BN;

    float    acc[2][8][4];
    uint32_t acx[2][8][2];    // cross, fp16 accum (scaled by 2^11)
    #pragma unroll
    for (int t = 0; t < 2; t++)
        #pragma unroll
        for (int n = 0; n < 8; n++) {
            #pragma unroll
            for (int q = 0; q < 4; q++) acc[t][n][q] = 0.0f;
            acx[t][n][0] = 0u; acx[t][n][1] = 0u;
        }

    const int nch = Ktot / S_BKC;

    auto load_chunk = [&](int ch) {
        const uint32_t stg = sb + (uint32_t)(ch % S_NSTG) * S_STG;
        const size_t k0 = (size_t)ch * S_BKC;
        #pragma unroll
        for (int i = 0; i < 2; i++) {
            int pos = tid + i * GT;
            int row = pos >> 2, seg = pos & 3;
            uint32_t soff = row * 64 + ((seg ^ ((row >> 1) & 3)) << 4);
            size_t ga = (size_t)(bm + row) * Ktot + k0 + seg * 8;
            size_t gb = (size_t)(bn + row) * Ktot + k0 + seg * 8;
            cp16(stg +         0 + soff, Ah + ga);
            cp16(stg +     S_BUF + soff, Al + ga);
            cp16(stg + 2 * S_BUF + soff, Bh + gb);
            cp16(stg + 3 * S_BUF + soff, Bl + gb);
        }
    };

    load_chunk(0); cp_commit();
    load_chunk(1); cp_commit();

    for (int ch = 0; ch < nch; ++ch) {
        cp_wait<1>();
        __syncthreads();
        if (ch + 2 < nch) load_chunk(ch + 2);
        cp_commit();

        const uint32_t stg = sb + (uint32_t)(ch % S_NSTG) * S_STG;

        #pragma unroll
        for (int k16 = 0; k16 < 2; ++k16) {
            uint32_t afh[2][4], afl[2][4], bfh[4][4], bfl[4][4];
            #pragma unroll
            for (int t = 0; t < 2; ++t) {
                int row = wm * 32 + t * 16 + (lane & 15);
                int seg = k16 * 2 + (lane >> 4);
                uint32_t off = row * 64 + ((seg ^ ((row >> 1) & 3)) << 4);
                ldsm4(afh[t], stg + off);
                ldsm4(afl[t], stg + S_BUF + off);
            }
            #pragma unroll
            for (int p = 0; p < 4; ++p) {
                int row = wn * 64 + p * 16 + ((lane >> 4) << 3) + (lane & 7);
                int seg = k16 * 2 + ((lane >> 3) & 1);
                uint32_t off = row * 64 + ((seg ^ ((row >> 1) & 3)) << 4);
                ldsm4(bfh[p], stg + 2 * S_BUF + off);
                ldsm4(bfl[p], stg + 3 * S_BUF + off);
            }
            #pragma unroll
            for (int t = 0; t < 2; ++t)
                #pragma unroll
                for (int nt = 0; nt < 8; ++nt)
                    mma16816_f32(acc[t][nt], afh[t], &bfh[nt >> 1][(nt & 1) * 2]);
            #pragma unroll
            for (int t = 0; t < 2; ++t)
                #pragma unroll
                for (int nt = 0; nt < 8; ++nt)
                    mma16816_f16(acx[t][nt], afh[t], &bfl[nt >> 1][(nt & 1) * 2]);
            #pragma unroll
            for (int t = 0; t < 2; ++t)
                #pragma unroll
                for (int nt = 0; nt < 8; ++nt)
                    mma16816_f16(acx[t][nt], afl[t], &bfh[nt >> 1][(nt & 1) * 2]);
        }
    }

    #pragma unroll
    for (int t = 0; t < 2; ++t) {
        #pragma unroll
        for (int nt = 0; nt < 8; ++nt) {
            float* c = acc[t][nt];
            __half2 cx01 = *reinterpret_cast<__half2*>(&acx[t][nt][0]);
            __half2 cx23 = *reinterpret_cast<__half2*>(&acx[t][nt][1]);
            const float a = 1.0f / 90.0f;
            float x0 = (c[0] + __half2float(cx01.x) * INVC) * a;
            float x1 = (c[1] + __half2float(cx01.y) * INVC) * a;
            float y0 = (c[2] + __half2float(cx23.x) * INVC) * a;
            float y1 = (c[3] + __half2float(cx23.y) * INVC) * a;
            const int n  = bn + wn * 64 + nt * 8 + (lane & 3) * 2;
            const int m0 = bm + wm * 32 + t * 16 + (lane >> 2);
            *(float2*)&g_s[(size_t)m0 * N_SEQ + n]       = make_float2(x0, x1);
            *(float2*)&g_s[(size_t)(m0 + 8) * N_SEQ + n] = make_float2(y0, y1);
        }
    }
}

// ---------------- fast exp on the FMA pipe (no MUFU) -------------------------
__device__ __forceinline__ float fast_exp(float x) {
    x = fmaxf(x, -87.0f);
    const float L2E = 1.4426950408889634f;
    float t = x * L2E;
    float z = t + 12582912.0f;
    float n = z - 12582912.0f;
    float f = t - n;
    int   i = __float_as_int(z) - 0x4B400000;
    float p = 1.3333558146e-3f;
    p = fmaf(p, f, 9.6181291076e-3f);
    p = fmaf(p, f, 5.5504108665e-2f);
    p = fmaf(p, f, 2.4022650696e-1f);
    p = fmaf(p, f, 6.9314718056e-1f);
    p = fmaf(p, f, 1.0f);
    float sc = __int_as_float((i + 127) << 23);
    return p * sc;
}

__device__ __forceinline__ void combine(float& m, float& Z, float& c, int& bi,
                                        float m2, float Z2, float c2, int bi2) {
    float M  = fmaxf(m, m2);
    float r1 = fast_exp(m  - M);
    float r2 = fast_exp(m2 - M);
    Z = Z * r1 + Z2 * r2;
    float ca = c  * r1;
    float cb = c2 * r2;
    if (cb > ca || (cb == ca && bi2 < bi)) { c = cb; bi = bi2; }
    else                                   { c = ca; }
    m = M;
}

__global__ __launch_bounds__(256)
void softmax_combine_kernel(float* __restrict__ out)
{
    const int row = blockIdx.x;
    const float4* __restrict__ S4 = (const float4*)(g_s + (size_t)row * N_SEQ);
    const float4* __restrict__ V4 = (const float4*)(g_v + (size_t)row * N_SEQ);
    const int tid = threadIdx.x;

    float m = -INFINITY, Z = 0.0f, c = -INFINITY;
    int bi = 0;

    #pragma unroll
    for (int it = 0; it < 4; it++) {
        int q = tid + it * 256;
        float4 s4 = S4[q];
        float4 v4 = V4[q];
        float ss[4] = {s4.x, s4.y, s4.z, s4.w};
        float vv[4] = {v4.x, v4.y, v4.z, v4.w};
        #pragma unroll
        for (int l = 0; l < 4; l++) {
            float s = ss[l];
            int   j = q * 4 + l;
            if (s > m) {
                float r = fast_exp(m - s);
                Z = Z * r + 1.0f;
                c = c * r;
                float cand = vv[l];
                if (cand > c || (cand == c && j < bi)) { c = cand; bi = j; }
                m = s;
            } else {
                float e = fast_exp(s - m);
                Z += e;
                float cand = e * vv[l];
                if (cand > c || (cand == c && j < bi)) { c = cand; bi = j; }
            }
        }
    }

    const unsigned full = 0xffffffffu;
    #pragma unroll
    for (int off = 16; off > 0; off >>= 1) {
        float m2 = __shfl_down_sync(full, m, off);
        float Z2 = __shfl_down_sync(full, Z, off);
        float c2 = __shfl_down_sync(full, c, off);
        int   b2 = __shfl_down_sync(full, bi, off);
        combine(m, Z, c, bi, m2, Z2, c2, b2);
    }

    __shared__ float sm[8], sz[8], sc[8];
    __shared__ int   sbuf[8];
    int wid = tid >> 5, lane = tid & 31;
    if (lane == 0) { sm[wid] = m; sz[wid] = Z; sc[wid] = c; sbuf[wid] = bi; }
    __syncthreads();
    if (tid == 0) {
        #pragma unroll
        for (int w = 1; w < 8; w++)
            combine(m, Z, c, bi, sm[w], sz[w], sc[w], sbuf[w]);
        out[row]         = c / Z;
        out[N_SEQ + row] = (float)bi;
    }
}

// ---------------- launch ------------------------------------------------------
extern "C" void kernel_launch(void* const* d_in, const int* in_sizes, int n_in,
                              void* d_out, int out_size)
{
    const float* x  = (const float*)d_in[0];
    const float* Wk = (const float*)d_in[1];
    const float* bk = (const float*)d_in[2];
    const float* Wv = (const float*)d_in[3];
    const float* bv = (const float*)d_in[4];
    // d_in[5]/d_in[6] (Wq,bq) are dead in the reference (x_q = x@Wv+bv)
    float* out = (float*)d_out;

    static bool attr_done = false;
    if (!attr_done) {
        cudaFuncSetAttribute(gemm_proj_kernel<0>, cudaFuncAttributeMaxDynamicSharedMemorySize, P_SMEM);
        cudaFuncSetAttribute(gemm_proj_kernel<1>, cudaFuncAttributeMaxDynamicSharedMemorySize, P_SMEM);
        cudaFuncSetAttribute(gemm_sc_kernel, cudaFuncAttributeMaxDynamicSharedMemorySize, S_SMEM);
        attr_done = true;
    }

    // 1) split x into fp16 hi + fp8 hi/lo
    convert_x_kernel<<<8192, 256>>>(x);
    // 2) transpose+split weights (fp16 hi + fp8 hi/lo)
    dim3 tg(HALF_K / 32, SIZE_K / 32);
    transpose_split_kernel<0><<<tg, dim3(32, 8)>>>(Wk);
    transpose_split_kernel<1><<<tg, dim3(32, 8)>>>(Wv);
    // 3) projections: fp16 hh + fp8 cross
    dim3 gproj(N_SEQ / BM, HALF_K / BN);
    gemm_proj_kernel<0><<<gproj, GT, P_SMEM>>>(bk);
    gemm_proj_kernel<1><<<gproj, GT, P_SMEM>>>(bv);
    // 4) scores: fp16 3-term (argmax-critical, round-9 numerics)
    dim3 gsc(N_SEQ / BM, N_SEQ / BN);
    gemm_sc_kernel<<<gsc, GT, S_SMEM>>>();
    // 5) softmax + elementwise V + row max/argmax
    softmax_combine_kernel<<<N_SEQ, 256>>>(out);
}

// round 11
// speedup vs baseline: 1.1288x; 1.1288x over previous
#include <cuda_runtime.h>
#include <cuda_fp16.h>
#include <math.h>
#include <stdint.h>

#define N_SEQ  4096
#define SIZE_K 8192
#define HALF_K 4096

#define BM   128
#define BN   128
#define GT   256         // threads per GEMM CTA (8 warps)

// fp8 scales (proj cross): both products land at 2^27
#define SXH  32.0f              // 2^5   x -> fp8
#define SXL  65536.0f           // 2^16  (x - h16(x)) -> fp8
#define SWH  2048.0f            // 2^11  W -> fp8
#define SWL  4194304.0f         // 2^22  (W - h16(W)) -> fp8
#define INV_CROSS (1.0f / 134217728.0f)  // 2^-27

// ---------------- scratch (static device globals; no runtime alloc) ----------
__device__ __half   g_xh[(size_t)N_SEQ * SIZE_K];          // fp16(x)
__device__ uint8_t  g_xh8[(size_t)N_SEQ * SIZE_K];         // e4m3(x * 2^5)
__device__ uint8_t  g_xl8[(size_t)N_SEQ * SIZE_K];         // e4m3((x-h) * 2^16)
__device__ __half   g_wkh[(size_t)HALF_K * SIZE_K];        // fp16(Wk^T)
__device__ uint8_t  g_wkh8[(size_t)HALF_K * SIZE_K];       // e4m3(W * 2^11)
__device__ uint8_t  g_wkl8[(size_t)HALF_K * SIZE_K];       // e4m3((W-h) * 2^22)
__device__ __half   g_wvh[(size_t)HALF_K * SIZE_K];
__device__ uint8_t  g_wvh8[(size_t)HALF_K * SIZE_K];
__device__ uint8_t  g_wvl8[(size_t)HALF_K * SIZE_K];
__device__ __half   g_kh[(size_t)N_SEQ * HALF_K];          // K hi (fp16)
__device__ __half   g_kl[(size_t)N_SEQ * HALF_K];          // K lo (unscaled fp16)
__device__ __half   g_vh[(size_t)N_SEQ * HALF_K];          // V hi
__device__ __half   g_vl[(size_t)N_SEQ * HALF_K];          // V lo
__device__ float    g_v [(size_t)N_SEQ * HALF_K];          // V fp32
__device__ float    g_s [(size_t)N_SEQ * N_SEQ];           // scores fp32

// ---------------- PTX helpers (base sm_103 features only) --------------------
static __device__ __forceinline__ uint32_t smem_u32(const void* p) {
    uint32_t a;
    asm("{ .reg .u64 t; cvta.to.shared.u64 t, %1; cvt.u32.u64 %0, t; }" : "=r"(a) : "l"(p));
    return a;
}
static __device__ __forceinline__ void cp16(uint32_t s, const void* g) {
    asm volatile("cp.async.cg.shared.global [%0], [%1], 16;" :: "r"(s), "l"(g));
}
static __device__ __forceinline__ void cp_commit() {
    asm volatile("cp.async.commit_group;" ::: "memory");
}
template<int NP> static __device__ __forceinline__ void cp_wait() {
    asm volatile("cp.async.wait_group %0;" :: "n"(NP) : "memory");
}
static __device__ __forceinline__ void ldsm4(uint32_t* r, uint32_t addr) {
    asm volatile("ldmatrix.sync.aligned.m8n8.x4.shared.b16 {%0,%1,%2,%3}, [%4];"
        : "=r"(r[0]), "=r"(r[1]), "=r"(r[2]), "=r"(r[3]) : "r"(addr));
}
static __device__ __forceinline__ void mma16816_f32(float* c, const uint32_t* a, const uint32_t* b) {
    asm volatile(
        "mma.sync.aligned.m16n8k16.row.col.f32.f16.f16.f32 "
        "{%0,%1,%2,%3}, {%4,%5,%6,%7}, {%8,%9}, {%0,%1,%2,%3};"
        : "+f"(c[0]), "+f"(c[1]), "+f"(c[2]), "+f"(c[3])
        : "r"(a[0]), "r"(a[1]), "r"(a[2]), "r"(a[3]), "r"(b[0]), "r"(b[1]));
}
static __device__ __forceinline__ void mma16832_e4m3(float* c, const uint32_t* a, const uint32_t* b) {
    asm volatile(
        "mma.sync.aligned.m16n8k32.row.col.f32.e4m3.e4m3.f32 "
        "{%0,%1,%2,%3}, {%4,%5,%6,%7}, {%8,%9}, {%0,%1,%2,%3};"
        : "+f"(c[0]), "+f"(c[1]), "+f"(c[2]), "+f"(c[3])
        : "r"(a[0]), "r"(a[1]), "r"(a[2]), "r"(a[3]), "r"(b[0]), "r"(b[1]));
}
// .b16 dest: low byte = cvt(lo), high byte = cvt(hi)
static __device__ __forceinline__ uint16_t e4m3x2(float hi, float lo) {
    uint16_t r;
    asm("cvt.rn.satfinite.e4m3x2.f32 %0, %1, %2;" : "=h"(r) : "f"(hi), "f"(lo));
    return r;
}
static __device__ __forceinline__ uint32_t pack4_e4m3(float e0, float e1, float e2, float e3) {
    return (uint32_t)e4m3x2(e1, e0) | ((uint32_t)e4m3x2(e3, e2) << 16);
}
static __device__ __forceinline__ void split2h(float x0, float x1, uint32_t& h, uint32_t& l) {
    __half h0 = __float2half_rn(x0), h1 = __float2half_rn(x1);
    __half l0 = __float2half_rn(x0 - __half2float(h0));
    __half l1 = __float2half_rn(x1 - __half2float(h1));
    h = (uint32_t)__half_as_ushort(h0) | ((uint32_t)__half_as_ushort(h1) << 16);
    l = (uint32_t)__half_as_ushort(l0) | ((uint32_t)__half_as_ushort(l1) << 16);
}

// ---------------- convert / split kernels ------------------------------------
__global__ __launch_bounds__(256)
void convert_x_kernel(const float* __restrict__ x)
{
    const size_t total4 = (size_t)N_SEQ * SIZE_K / 4;
    uint32_t* xh2  = reinterpret_cast<uint32_t*>(g_xh);
    uint32_t* xh8w = reinterpret_cast<uint32_t*>(g_xh8);
    uint32_t* xl8w = reinterpret_cast<uint32_t*>(g_xl8);
    for (size_t i = (size_t)blockIdx.x * blockDim.x + threadIdx.x; i < total4;
         i += (size_t)gridDim.x * blockDim.x) {
        float4 v = reinterpret_cast<const float4*>(x)[i];
        __half h0 = __float2half_rn(v.x), h1 = __float2half_rn(v.y);
        __half h2 = __float2half_rn(v.z), h3 = __float2half_rn(v.w);
        float l0 = v.x - __half2float(h0);
        float l1 = v.y - __half2float(h1);
        float l2 = v.z - __half2float(h2);
        float l3 = v.w - __half2float(h3);
        xh2[2*i]   = (uint32_t)__half_as_ushort(h0) | ((uint32_t)__half_as_ushort(h1) << 16);
        xh2[2*i+1] = (uint32_t)__half_as_ushort(h2) | ((uint32_t)__half_as_ushort(h3) << 16);
        xh8w[i] = pack4_e4m3(v.x * SXH, v.y * SXH, v.z * SXH, v.w * SXH);
        xl8w[i] = pack4_e4m3(l0 * SXL, l1 * SXL, l2 * SXL, l3 * SXL);
    }
}

// W [SIZE_K, HALF_K] fp32 -> WT [HALF_K, SIZE_K]: fp16 hi + fp8 hi/lo
template<int WSEL>
__global__ __launch_bounds__(256)
void transpose_split_kernel(const float* __restrict__ W)
{
    __half*  dh  = (WSEL == 0) ? g_wkh  : g_wvh;
    uint8_t* dh8 = (WSEL == 0) ? g_wkh8 : g_wvh8;
    uint8_t* dl8 = (WSEL == 0) ? g_wkl8 : g_wvl8;
    __shared__ float t[32][33];
    int n0 = blockIdx.x * 32;
    int k0 = blockIdx.y * 32;
    int tx = threadIdx.x, ty = threadIdx.y;   // block (32, 8)
    #pragma unroll
    for (int i = 0; i < 4; i++)
        t[ty + i * 8][tx] = W[(size_t)(k0 + ty + i * 8) * HALF_K + n0 + tx];
    __syncthreads();
    #pragma unroll
    for (int i = 0; i < 4; i++) {
        int n = n0 + ty + i * 8;
        int k = k0 + tx;
        float v = t[tx][ty + i * 8];
        __half h = __float2half_rn(v);
        float l = v - __half2float(h);
        dh[(size_t)n * SIZE_K + k]  = h;
        dh8[(size_t)n * SIZE_K + k] = (uint8_t)(e4m3x2(0.0f, v * SWH) & 0xFF);
        dl8[(size_t)n * SIZE_K + k] = (uint8_t)(e4m3x2(0.0f, l * SWL) & 0xFF);
    }
}

// ---------------- projection GEMM: fp16 hh + fp8 cross (per-chunk fold) ------
// MODE 0: K proj (out: g_kh/g_kl, bias=bk)   MODE 1: V proj (out: g_v,g_vh/g_vl)
// smem stage (32 KB, chunk K=32): Ah 8K | Bh 8K | Ah8 4K | Al8 4K | Bh8 4K | Bl8 4K
#define P_STG 32768u
#define P_NSTG 4
#define P_SMEM (P_NSTG * P_STG)
#define OA8  16384u
#define OAL8 20480u
#define OB8  24576u
#define OBL8 28672u
#define P_BKC 32

template<int MODE>
__global__ __launch_bounds__(GT, 1)
void gemm_proj_kernel(const float* __restrict__ bias)
{
    const __half* Ah = g_xh;
    const uint8_t *A8 = g_xh8, *Al8 = g_xl8;
    const __half* Bh = (MODE == 0) ? g_wkh : g_wvh;
    const uint8_t *B8  = (MODE == 0) ? g_wkh8 : g_wvh8;
    const uint8_t *Bl8 = (MODE == 0) ? g_wkl8 : g_wvl8;
    const int Ktot = SIZE_K;

    extern __shared__ char smem[];
    const uint32_t sb = smem_u32(smem);
    const int tid  = threadIdx.x;
    const int wid  = tid >> 5;
    const int lane = tid & 31;
    const int wm   = wid & 3;     // warp row 0..3 (32 rows)
    const int wn   = wid >> 2;    // warp col 0..1 (64 cols)

    const int bm = blockIdx.x * BM;
    const int bn = blockIdx.y * BN;

    float acc[2][8][4];   // shared accumulator (hh natural scale; cross folded)
    #pragma unroll
    for (int t = 0; t < 2; t++)
        #pragma unroll
        for (int n = 0; n < 8; n++)
            #pragma unroll
            for (int q = 0; q < 4; q++) acc[t][n][q] = 0.0f;

    const int nch = Ktot / P_BKC;

    auto load_chunk = [&](int ch) {
        const uint32_t stg = sb + (uint32_t)(ch % P_NSTG) * P_STG;
        const size_t k0 = (size_t)ch * P_BKC;
        #pragma unroll
        for (int i = 0; i < 2; i++) {
            int pos = tid + i * GT;            // 0..511
            int row = pos >> 2, seg = pos & 3;
            uint32_t soff = row * 64 + ((seg ^ ((row >> 1) & 3)) << 4);
            cp16(stg + soff,         Ah + (size_t)(bm + row) * Ktot + k0 + seg * 8);
            cp16(stg + 8192u + soff, Bh + (size_t)(bn + row) * Ktot + k0 + seg * 8);
        }
        {
            int row = tid >> 1, c = tid & 1;
            uint32_t soff = row * 32 + ((c ^ ((row >> 2) & 1)) << 4);
            size_t ga = (size_t)(bm + row) * Ktot + k0 + c * 16;
            size_t gb = (size_t)(bn + row) * Ktot + k0 + c * 16;
            cp16(stg + OA8  + soff, A8  + ga);
            cp16(stg + OAL8 + soff, Al8 + ga);
            cp16(stg + OB8  + soff, B8  + gb);
            cp16(stg + OBL8 + soff, Bl8 + gb);
        }
    };

    load_chunk(0); cp_commit();
    load_chunk(1); cp_commit();
    load_chunk(2); cp_commit();

    for (int ch = 0; ch < nch; ++ch) {
        cp_wait<2>();
        __syncthreads();
        if (ch + 3 < nch) load_chunk(ch + 3);
        cp_commit();

        const uint32_t stg = sb + (uint32_t)(ch % P_NSTG) * P_STG;

        // ---- fp8 cross terms: per-t transient accumulator, fold into acc
        {
            uint32_t bh8[4][4], bl8[4][4];
            #pragma unroll
            for (int p = 0; p < 4; ++p) {
                int row = wn * 64 + p * 16 + ((lane >> 4) << 3) + (lane & 7);
                int kh  = (lane >> 3) & 1;
                uint32_t off = row * 32 + ((kh ^ ((row >> 2) & 1)) << 4);
                ldsm4(bh8[p], stg + OB8  + off);
                ldsm4(bl8[p], stg + OBL8 + off);
            }
            #pragma unroll
            for (int t = 0; t < 2; ++t) {
                uint32_t ah8[4], al8[4];
                {
                    int row = wm * 32 + t * 16 + (lane & 15);
                    int kh  = lane >> 4;
                    uint32_t off = row * 32 + ((kh ^ ((row >> 2) & 1)) << 4);
                    ldsm4(ah8, stg + OA8  + off);
                    ldsm4(al8, stg + OAL8 + off);
                }
                float acx[8][4];
                #pragma unroll
                for (int nt = 0; nt < 8; ++nt)
                    #pragma unroll
                    for (int q = 0; q < 4; ++q) acx[nt][q] = 0.0f;
                #pragma unroll
                for (int nt = 0; nt < 8; ++nt)
                    mma16832_e4m3(acx[nt], ah8, &bl8[nt >> 1][(nt & 1) * 2]);
                #pragma unroll
                for (int nt = 0; nt < 8; ++nt)
                    mma16832_e4m3(acx[nt], al8, &bh8[nt >> 1][(nt & 1) * 2]);
                #pragma unroll
                for (int nt = 0; nt < 8; ++nt)
                    #pragma unroll
                    for (int q = 0; q < 4; ++q)
                        acc[t][nt][q] = fmaf(acx[nt][q], INV_CROSS, acc[t][nt][q]);
            }
        }

        // ---- fp16 hi*hi
        #pragma unroll
        for (int k16 = 0; k16 < 2; ++k16) {
            uint32_t afh[2][4], bfh[4][4];
            #pragma unroll
            for (int t = 0; t < 2; ++t) {
                int row = wm * 32 + t * 16 + (lane & 15);
                int seg = k16 * 2 + (lane >> 4);
                uint32_t off = row * 64 + ((seg ^ ((row >> 1) & 3)) << 4);
                ldsm4(afh[t], stg + off);
            }
            #pragma unroll
            for (int p = 0; p < 4; ++p) {
                int row = wn * 64 + p * 16 + ((lane >> 4) << 3) + (lane & 7);
                int seg = k16 * 2 + ((lane >> 3) & 1);
                uint32_t off = row * 64 + ((seg ^ ((row >> 1) & 3)) << 4);
                ldsm4(bfh[p], stg + 8192u + off);
            }
            #pragma unroll
            for (int t = 0; t < 2; ++t)
                #pragma unroll
                for (int nt = 0; nt < 8; ++nt)
                    mma16816_f32(acc[t][nt], afh[t], &bfh[nt >> 1][(nt & 1) * 2]);
        }
    }

    // ---- epilogue
    #pragma unroll
    for (int t = 0; t < 2; ++t) {
        #pragma unroll
        for (int nt = 0; nt < 8; ++nt) {
            const int n  = bn + wn * 64 + nt * 8 + (lane & 3) * 2;
            const int m0 = bm + wm * 32 + t * 16 + (lane >> 2);
            float b0 = __ldg(&bias[n]), b1 = __ldg(&bias[n + 1]);
            float x0 = acc[t][nt][0] + b0;
            float x1 = acc[t][nt][1] + b1;
            float y0 = acc[t][nt][2] + b0;
            float y1 = acc[t][nt][3] + b1;
            if (MODE == 1) {
                *(float2*)&g_v[(size_t)m0 * HALF_K + n]       = make_float2(x0, x1);
                *(float2*)&g_v[(size_t)(m0 + 8) * HALF_K + n] = make_float2(y0, y1);
            }
            __half* dsth = (MODE == 0) ? g_kh : g_vh;
            __half* dstl = (MODE == 0) ? g_kl : g_vl;
            uint32_t h, l;
            split2h(x0, x1, h, l);
            *(uint32_t*)&dsth[(size_t)m0 * HALF_K + n] = h;
            *(uint32_t*)&dstl[(size_t)m0 * HALF_K + n] = l;
            split2h(y0, y1, h, l);
            *(uint32_t*)&dsth[(size_t)(m0 + 8) * HALF_K + n] = h;
            *(uint32_t*)&dstl[(size_t)(m0 + 8) * HALF_K + n] = l;
        }
    }
}

// ---------------- scores GEMM: fp16 3-term, single fp32 acc (lo unscaled) ----
#define S_STG 32768u
#define S_BUF 8192u
#define S_NSTG 3
#define S_SMEM (S_NSTG * S_STG)
#define S_BKC 32

__global__ __launch_bounds__(GT, 2)
void gemm_sc_kernel()
{
    const __half *Ah = g_vh, *Al = g_vl, *Bh = g_kh, *Bl = g_kl;
    const int Ktot = HALF_K;

    extern __shared__ char smem[];
    const uint32_t sb = smem_u32(smem);
    const int tid  = threadIdx.x;
    const int wid  = tid >> 5;
    const int lane = tid & 31;
    const int wm   = wid & 3;
    const int wn   = wid >> 2;

    const int bm = blockIdx.x * BM;
    const int bn = blockIdx.y * BN;

    float acc[2][8][4];
    #pragma unroll
    for (int t = 0; t < 2; t++)
        #pragma unroll
        for (int n = 0; n < 8; n++)
            #pragma unroll
            for (int q = 0; q < 4; q++) acc[t][n][q] = 0.0f;

    const int nch = Ktot / S_BKC;

    auto load_chunk = [&](int ch) {
        const uint32_t stg = sb + (uint32_t)(ch % S_NSTG) * S_STG;
        const size_t k0 = (size_t)ch * S_BKC;
        #pragma unroll
        for (int i = 0; i < 2; i++) {
            int pos = tid + i * GT;
            int row = pos >> 2, seg = pos & 3;
            uint32_t soff = row * 64 + ((seg ^ ((row >> 1) & 3)) << 4);
            size_t ga = (size_t)(bm + row) * Ktot + k0 + seg * 8;
            size_t gb = (size_t)(bn + row) * Ktot + k0 + seg * 8;
            cp16(stg +         0 + soff, Ah + ga);
            cp16(stg +     S_BUF + soff, Al + ga);
            cp16(stg + 2 * S_BUF + soff, Bh + gb);
            cp16(stg + 3 * S_BUF + soff, Bl + gb);
        }
    };

    load_chunk(0); cp_commit();
    load_chunk(1); cp_commit();

    for (int ch = 0; ch < nch; ++ch) {
        cp_wait<1>();
        __syncthreads();
        if (ch + 2 < nch) load_chunk(ch + 2);
        cp_commit();

        const uint32_t stg = sb + (uint32_t)(ch % S_NSTG) * S_STG;

        #pragma unroll
        for (int k16 = 0; k16 < 2; ++k16) {
            uint32_t afh[2][4], afl[2][4], bfh[4][4], bfl[4][4];
            #pragma unroll
            for (int t = 0; t < 2; ++t) {
                int row = wm * 32 + t * 16 + (lane & 15);
                int seg = k16 * 2 + (lane >> 4);
                uint32_t off = row * 64 + ((seg ^ ((row >> 1) & 3)) << 4);
                ldsm4(afh[t], stg + off);
                ldsm4(afl[t], stg + S_BUF + off);
            }
            #pragma unroll
            for (int p = 0; p < 4; ++p) {
                int row = wn * 64 + p * 16 + ((lane >> 4) << 3) + (lane & 7);
                int seg = k16 * 2 + ((lane >> 3) & 1);
                uint32_t off = row * 64 + ((seg ^ ((row >> 1) & 3)) << 4);
                ldsm4(bfh[p], stg + 2 * S_BUF + off);
                ldsm4(bfl[p], stg + 3 * S_BUF + off);
            }
            #pragma unroll
            for (int t = 0; t < 2; ++t)
                #pragma unroll
                for (int nt = 0; nt < 8; ++nt)
                    mma16816_f32(acc[t][nt], afh[t], &bfh[nt >> 1][(nt & 1) * 2]);
            #pragma unroll
            for (int t = 0; t < 2; ++t)
                #pragma unroll
                for (int nt = 0; nt < 8; ++nt)
                    mma16816_f32(acc[t][nt], afh[t], &bfl[nt >> 1][(nt & 1) * 2]);
            #pragma unroll
            for (int t = 0; t < 2; ++t)
                #pragma unroll
                for (int nt = 0; nt < 8; ++nt)
                    mma16816_f32(acc[t][nt], afl[t], &bfh[nt >> 1][(nt & 1) * 2]);
        }
    }

    #pragma unroll
    for (int t = 0; t < 2; ++t) {
        #pragma unroll
        for (int nt = 0; nt < 8; ++nt) {
            float* c = acc[t][nt];
            const int n  = bn + wn * 64 + nt * 8 + (lane & 3) * 2;
            const int m0 = bm + wm * 32 + t * 16 + (lane >> 2);
            const float a = 1.0f / 90.0f;
            *(float2*)&g_s[(size_t)m0 * N_SEQ + n]       = make_float2(c[0] * a, c[1] * a);
            *(float2*)&g_s[(size_t)(m0 + 8) * N_SEQ + n] = make_float2(c[2] * a, c[3] * a);
        }
    }
}

// ---------------- fast exp on the FMA pipe (no MUFU) -------------------------
__device__ __forceinline__ float fast_exp(float x) {
    x = fmaxf(x, -87.0f);
    const float L2E = 1.4426950408889634f;
    float t = x * L2E;
    float z = t + 12582912.0f;
    float n = z - 12582912.0f;
    float f = t - n;
    int   i = __float_as_int(z) - 0x4B400000;
    float p = 1.3333558146e-3f;
    p = fmaf(p, f, 9.6181291076e-3f);
    p = fmaf(p, f, 5.5504108665e-2f);
    p = fmaf(p, f, 2.4022650696e-1f);
    p = fmaf(p, f, 6.9314718056e-1f);
    p = fmaf(p, f, 1.0f);
    float sc = __int_as_float((i + 127) << 23);
    return p * sc;
}

__device__ __forceinline__ void combine(float& m, float& Z, float& c, int& bi,
                                        float m2, float Z2, float c2, int bi2) {
    float M  = fmaxf(m, m2);
    float r1 = fast_exp(m  - M);
    float r2 = fast_exp(m2 - M);
    Z = Z * r1 + Z2 * r2;
    float ca = c  * r1;
    float cb = c2 * r2;
    if (cb > ca || (cb == ca && bi2 < bi)) { c = cb; bi = bi2; }
    else                                   { c = ca; }
    m = M;
}

__global__ __launch_bounds__(256)
void softmax_combine_kernel(float* __restrict__ out)
{
    const int row = blockIdx.x;
    const float4* __restrict__ S4 = (const float4*)(g_s + (size_t)row * N_SEQ);
    const float4* __restrict__ V4 = (const float4*)(g_v + (size_t)row * N_SEQ);
    const int tid = threadIdx.x;

    float m = -INFINITY, Z = 0.0f, c = -INFINITY;
    int bi = 0;

    #pragma unroll
    for (int it = 0; it < 4; it++) {
        int q = tid + it * 256;
        float4 s4 = S4[q];
        float4 v4 = V4[q];
        float ss[4] = {s4.x, s4.y, s4.z, s4.w};
        float vv[4] = {v4.x, v4.y, v4.z, v4.w};
        #pragma unroll
        for (int l = 0; l < 4; l++) {
            float s = ss[l];
            int   j = q * 4 + l;
            if (s > m) {
                float r = fast_exp(m - s);
                Z = Z * r + 1.0f;
                c = c * r;
                float cand = vv[l];
                if (cand > c || (cand == c && j < bi)) { c = cand; bi = j; }
                m = s;
            } else {
                float e = fast_exp(s - m);
                Z += e;
                float cand = e * vv[l];
                if (cand > c || (cand == c && j < bi)) { c = cand; bi = j; }
            }
        }
    }

    const unsigned full = 0xffffffffu;
    #pragma unroll
    for (int off = 16; off > 0; off >>= 1) {
        float m2 = __shfl_down_sync(full, m, off);
        float Z2 = __shfl_down_sync(full, Z, off);
        float c2 = __shfl_down_sync(full, c, off);
        int   b2 = __shfl_down_sync(full, bi, off);
        combine(m, Z, c, bi, m2, Z2, c2, b2);
    }

    __shared__ float sm[8], sz[8], sc[8];
    __shared__ int   sbuf[8];
    int wid = tid >> 5, lane = tid & 31;
    if (lane == 0) { sm[wid] = m; sz[wid] = Z; sc[wid] = c; sbuf[wid] = bi; }
    __syncthreads();
    if (tid == 0) {
        #pragma unroll
        for (int w = 1; w < 8; w++)
            combine(m, Z, c, bi, sm[w], sz[w], sc[w], sbuf[w]);
        out[row]         = c / Z;
        out[N_SEQ + row] = (float)bi;
    }
}

// ---------------- launch ------------------------------------------------------
extern "C" void kernel_launch(void* const* d_in, const int* in_sizes, int n_in,
                              void* d_out, int out_size)
{
    const float* x  = (const float*)d_in[0];
    const float* Wk = (const float*)d_in[1];
    const float* bk = (const float*)d_in[2];
    const float* Wv = (const float*)d_in[3];
    const float* bv = (const float*)d_in[4];
    // d_in[5]/d_in[6] (Wq,bq) are dead in the reference (x_q = x@Wv+bv)
    float* out = (float*)d_out;

    static bool attr_done = false;
    if (!attr_done) {
        cudaFuncSetAttribute(gemm_proj_kernel<0>, cudaFuncAttributeMaxDynamicSharedMemorySize, P_SMEM);
        cudaFuncSetAttribute(gemm_proj_kernel<1>, cudaFuncAttributeMaxDynamicSharedMemorySize, P_SMEM);
        cudaFuncSetAttribute(gemm_sc_kernel, cudaFuncAttributeMaxDynamicSharedMemorySize, S_SMEM);
        attr_done = true;
    }

    // 1) split x into fp16 hi + fp8 hi/lo
    convert_x_kernel<<<8192, 256>>>(x);
    // 2) transpose+split weights (fp16 hi + fp8 hi/lo)
    dim3 tg(HALF_K / 32, SIZE_K / 32);
    transpose_split_kernel<0><<<tg, dim3(32, 8)>>>(Wk);
    transpose_split_kernel<1><<<tg, dim3(32, 8)>>>(Wv);
    // 3) projections: fp16 hh + fp8 cross (per-chunk fold, low regs)
    dim3 gproj(N_SEQ / BM, HALF_K / BN);
    gemm_proj_kernel<0><<<gproj, GT, P_SMEM>>>(bk);
    gemm_proj_kernel<1><<<gproj, GT, P_SMEM>>>(bv);
    // 4) scores: fp16 3-term, single fp32 acc
    dim3 gsc(N_SEQ / BM, N_SEQ / BN);
    gemm_sc_kernel<<<gsc, GT, S_SMEM>>>();
    // 5) softmax + elementwise V + row max/argmax
    softmax_combine_kernel<<<N_SEQ, 256>>>(out);
}

// round 12
// speedup vs baseline: 1.1695x; 1.0360x over previous
#include <cuda_runtime.h>
#include <cuda_fp16.h>
#include <math.h>
#include <stdint.h>

#define N_SEQ  4096
#define SIZE_K 8192
#define HALF_K 4096

#define BM   128
#define BN   128
#define GT   256         // threads per GEMM CTA (8 warps)

// fp8 scales (proj cross): both products land at 2^27
#define SXH  32.0f              // 2^5   x -> fp8
#define SXL  65536.0f           // 2^16  (x - h16(x)) -> fp8
#define SWH  2048.0f            // 2^11  W -> fp8
#define SWL  4194304.0f         // 2^22  (W - h16(W)) -> fp8
#define INV_CROSS (1.0f / 134217728.0f)  // 2^-27

// ---------------- scratch (static device globals; no runtime alloc) ----------
__device__ __half   g_xh[(size_t)N_SEQ * SIZE_K];          // fp16(x)
__device__ uint8_t  g_xh8[(size_t)N_SEQ * SIZE_K];         // e4m3(x * 2^5)
__device__ uint8_t  g_xl8[(size_t)N_SEQ * SIZE_K];         // e4m3((x-h) * 2^16)
__device__ __half   g_wkh[(size_t)HALF_K * SIZE_K];        // fp16(Wk^T)
__device__ uint8_t  g_wkh8[(size_t)HALF_K * SIZE_K];       // e4m3(W * 2^11)
__device__ uint8_t  g_wkl8[(size_t)HALF_K * SIZE_K];       // e4m3((W-h) * 2^22)
__device__ __half   g_wvh[(size_t)HALF_K * SIZE_K];
__device__ uint8_t  g_wvh8[(size_t)HALF_K * SIZE_K];
__device__ uint8_t  g_wvl8[(size_t)HALF_K * SIZE_K];
__device__ __half   g_kh[(size_t)N_SEQ * HALF_K];          // K hi (fp16)
__device__ __half   g_kl[(size_t)N_SEQ * HALF_K];          // K lo (unscaled fp16)
__device__ __half   g_vh[(size_t)N_SEQ * HALF_K];          // V hi
__device__ __half   g_vl[(size_t)N_SEQ * HALF_K];          // V lo
__device__ float    g_k [(size_t)N_SEQ * HALF_K];          // K fp32 partial/final
__device__ float    g_v [(size_t)N_SEQ * HALF_K];          // V fp32
__device__ float    g_s [(size_t)N_SEQ * N_SEQ];           // scores fp32

// ---------------- PTX helpers (base sm_103 features only) --------------------
static __device__ __forceinline__ uint32_t smem_u32(const void* p) {
    uint32_t a;
    asm("{ .reg .u64 t; cvta.to.shared.u64 t, %1; cvt.u32.u64 %0, t; }" : "=r"(a) : "l"(p));
    return a;
}
static __device__ __forceinline__ void cp16(uint32_t s, const void* g) {
    asm volatile("cp.async.cg.shared.global [%0], [%1], 16;" :: "r"(s), "l"(g));
}
static __device__ __forceinline__ void cp_commit() {
    asm volatile("cp.async.commit_group;" ::: "memory");
}
template<int NP> static __device__ __forceinline__ void cp_wait() {
    asm volatile("cp.async.wait_group %0;" :: "n"(NP) : "memory");
}
static __device__ __forceinline__ void ldsm4(uint32_t* r, uint32_t addr) {
    asm volatile("ldmatrix.sync.aligned.m8n8.x4.shared.b16 {%0,%1,%2,%3}, [%4];"
        : "=r"(r[0]), "=r"(r[1]), "=r"(r[2]), "=r"(r[3]) : "r"(addr));
}
static __device__ __forceinline__ void mma16816_f32(float* c, const uint32_t* a, const uint32_t* b) {
    asm volatile(
        "mma.sync.aligned.m16n8k16.row.col.f32.f16.f16.f32 "
        "{%0,%1,%2,%3}, {%4,%5,%6,%7}, {%8,%9}, {%0,%1,%2,%3};"
        : "+f"(c[0]), "+f"(c[1]), "+f"(c[2]), "+f"(c[3])
        : "r"(a[0]), "r"(a[1]), "r"(a[2]), "r"(a[3]), "r"(b[0]), "r"(b[1]));
}
static __device__ __forceinline__ void mma16832_e4m3(float* c, const uint32_t* a, const uint32_t* b) {
    asm volatile(
        "mma.sync.aligned.m16n8k32.row.col.f32.e4m3.e4m3.f32 "
        "{%0,%1,%2,%3}, {%4,%5,%6,%7}, {%8,%9}, {%0,%1,%2,%3};"
        : "+f"(c[0]), "+f"(c[1]), "+f"(c[2]), "+f"(c[3])
        : "r"(a[0]), "r"(a[1]), "r"(a[2]), "r"(a[3]), "r"(b[0]), "r"(b[1]));
}
// .b16 dest: low byte = cvt(lo), high byte = cvt(hi)
static __device__ __forceinline__ uint16_t e4m3x2(float hi, float lo) {
    uint16_t r;
    asm("cvt.rn.satfinite.e4m3x2.f32 %0, %1, %2;" : "=h"(r) : "f"(hi), "f"(lo));
    return r;
}
static __device__ __forceinline__ uint32_t pack4_e4m3(float e0, float e1, float e2, float e3) {
    return (uint32_t)e4m3x2(e1, e0) | ((uint32_t)e4m3x2(e3, e2) << 16);
}
static __device__ __forceinline__ void split2h(float x0, float x1, uint32_t& h, uint32_t& l) {
    __half h0 = __float2half_rn(x0), h1 = __float2half_rn(x1);
    __half l0 = __float2half_rn(x0 - __half2float(h0));
    __half l1 = __float2half_rn(x1 - __half2float(h1));
    h = (uint32_t)__half_as_ushort(h0) | ((uint32_t)__half_as_ushort(h1) << 16);
    l = (uint32_t)__half_as_ushort(l0) | ((uint32_t)__half_as_ushort(l1) << 16);
}

// ---------------- convert / split kernels ------------------------------------
__global__ __launch_bounds__(256)
void convert_x_kernel(const float* __restrict__ x)
{
    const size_t total4 = (size_t)N_SEQ * SIZE_K / 4;
    uint32_t* xh2  = reinterpret_cast<uint32_t*>(g_xh);
    uint32_t* xh8w = reinterpret_cast<uint32_t*>(g_xh8);
    uint32_t* xl8w = reinterpret_cast<uint32_t*>(g_xl8);
    for (size_t i = (size_t)blockIdx.x * blockDim.x + threadIdx.x; i < total4;
         i += (size_t)gridDim.x * blockDim.x) {
        float4 v = reinterpret_cast<const float4*>(x)[i];
        __half h0 = __float2half_rn(v.x), h1 = __float2half_rn(v.y);
        __half h2 = __float2half_rn(v.z), h3 = __float2half_rn(v.w);
        float l0 = v.x - __half2float(h0);
        float l1 = v.y - __half2float(h1);
        float l2 = v.z - __half2float(h2);
        float l3 = v.w - __half2float(h3);
        xh2[2*i]   = (uint32_t)__half_as_ushort(h0) | ((uint32_t)__half_as_ushort(h1) << 16);
        xh2[2*i+1] = (uint32_t)__half_as_ushort(h2) | ((uint32_t)__half_as_ushort(h3) << 16);
        xh8w[i] = pack4_e4m3(v.x * SXH, v.y * SXH, v.z * SXH, v.w * SXH);
        xl8w[i] = pack4_e4m3(l0 * SXL, l1 * SXL, l2 * SXL, l3 * SXL);
    }
}

// W [SIZE_K, HALF_K] fp32 -> WT [HALF_K, SIZE_K]: fp16 hi + fp8 hi/lo
template<int WSEL>
__global__ __launch_bounds__(256)
void transpose_split_kernel(const float* __restrict__ W)
{
    __half*  dh  = (WSEL == 0) ? g_wkh  : g_wvh;
    uint8_t* dh8 = (WSEL == 0) ? g_wkh8 : g_wvh8;
    uint8_t* dl8 = (WSEL == 0) ? g_wkl8 : g_wvl8;
    __shared__ float t[32][33];
    int n0 = blockIdx.x * 32;
    int k0 = blockIdx.y * 32;
    int tx = threadIdx.x, ty = threadIdx.y;   // block (32, 8)
    #pragma unroll
    for (int i = 0; i < 4; i++)
        t[ty + i * 8][tx] = W[(size_t)(k0 + ty + i * 8) * HALF_K + n0 + tx];
    __syncthreads();
    #pragma unroll
    for (int i = 0; i < 4; i++) {
        int n = n0 + ty + i * 8;
        int k = k0 + tx;
        float v = t[tx][ty + i * 8];
        __half h = __float2half_rn(v);
        float l = v - __half2float(h);
        dh[(size_t)n * SIZE_K + k]  = h;
        dh8[(size_t)n * SIZE_K + k] = (uint8_t)(e4m3x2(0.0f, v * SWH) & 0xFF);
        dl8[(size_t)n * SIZE_K + k] = (uint8_t)(e4m3x2(0.0f, l * SWL) & 0xFF);
    }
}

// ---------------- Kernel A: fp16 hi*hi projection (1 term) --------------------
// MODE 0: g_k = x_h @ Wk_h^T + bk        MODE 1: g_v = x_h @ Wv_h^T + bv
#define A_STG 16384u
#define A_NSTG 3
#define A_SMEM (A_NSTG * A_STG)
#define A_BKC 32

template<int MODE>
__global__ __launch_bounds__(GT, 2)
void gemm_hh_kernel(const float* __restrict__ bias)
{
    const __half* Ah = g_xh;
    const __half* Bh = (MODE == 0) ? g_wkh : g_wvh;
    const int Ktot = SIZE_K;

    extern __shared__ char smem[];
    const uint32_t sb = smem_u32(smem);
    const int tid  = threadIdx.x;
    const int wid  = tid >> 5;
    const int lane = tid & 31;
    const int wm   = wid & 3;
    const int wn   = wid >> 2;

    const int bm = blockIdx.x * BM;
    const int bn = blockIdx.y * BN;

    float acc[2][8][4];
    #pragma unroll
    for (int t = 0; t < 2; t++)
        #pragma unroll
        for (int n = 0; n < 8; n++)
            #pragma unroll
            for (int q = 0; q < 4; q++) acc[t][n][q] = 0.0f;

    const int nch = Ktot / A_BKC;

    auto load_chunk = [&](int ch) {
        const uint32_t stg = sb + (uint32_t)(ch % A_NSTG) * A_STG;
        const size_t k0 = (size_t)ch * A_BKC;
        #pragma unroll
        for (int i = 0; i < 2; i++) {
            int pos = tid + i * GT;            // 0..511
            int row = pos >> 2, seg = pos & 3;
            uint32_t soff = row * 64 + ((seg ^ ((row >> 1) & 3)) << 4);
            cp16(stg + soff,         Ah + (size_t)(bm + row) * Ktot + k0 + seg * 8);
            cp16(stg + 8192u + soff, Bh + (size_t)(bn + row) * Ktot + k0 + seg * 8);
        }
    };

    load_chunk(0); cp_commit();
    load_chunk(1); cp_commit();

    for (int ch = 0; ch < nch; ++ch) {
        cp_wait<1>();
        __syncthreads();
        if (ch + 2 < nch) load_chunk(ch + 2);
        cp_commit();

        const uint32_t stg = sb + (uint32_t)(ch % A_NSTG) * A_STG;

        #pragma unroll
        for (int k16 = 0; k16 < 2; ++k16) {
            uint32_t afh[2][4], bfh[4][4];
            #pragma unroll
            for (int t = 0; t < 2; ++t) {
                int row = wm * 32 + t * 16 + (lane & 15);
                int seg = k16 * 2 + (lane >> 4);
                uint32_t off = row * 64 + ((seg ^ ((row >> 1) & 3)) << 4);
                ldsm4(afh[t], stg + off);
            }
            #pragma unroll
            for (int p = 0; p < 4; ++p) {
                int row = wn * 64 + p * 16 + ((lane >> 4) << 3) + (lane & 7);
                int seg = k16 * 2 + ((lane >> 3) & 1);
                uint32_t off = row * 64 + ((seg ^ ((row >> 1) & 3)) << 4);
                ldsm4(bfh[p], stg + 8192u + off);
            }
            #pragma unroll
            for (int t = 0; t < 2; ++t)
                #pragma unroll
                for (int nt = 0; nt < 8; ++nt)
                    mma16816_f32(acc[t][nt], afh[t], &bfh[nt >> 1][(nt & 1) * 2]);
        }
    }

    float* dstf = (MODE == 0) ? g_k : g_v;
    #pragma unroll
    for (int t = 0; t < 2; ++t) {
        #pragma unroll
        for (int nt = 0; nt < 8; ++nt) {
            float* c = acc[t][nt];
            const int n  = bn + wn * 64 + nt * 8 + (lane & 3) * 2;
            const int m0 = bm + wm * 32 + t * 16 + (lane >> 2);
            float b0 = __ldg(&bias[n]), b1 = __ldg(&bias[n + 1]);
            *(float2*)&dstf[(size_t)m0 * HALF_K + n]       = make_float2(c[0] + b0, c[1] + b1);
            *(float2*)&dstf[(size_t)(m0 + 8) * HALF_K + n] = make_float2(c[2] + b0, c[3] + b1);
        }
    }
}

// ---------------- Kernel B: fp8 cross terms + final split ---------------------
// MODE 0: g_k += cross; emit g_kh/g_kl    MODE 1: g_v += cross; emit g_vh/g_vl
// stage (16 KB, chunk K=32): Ah8 4K | Al8 4K | Bh8 4K | Bl8 4K
#define B_STG 16384u
#define B_NSTG 4
#define B_SMEM (B_NSTG * B_STG)
#define B_BKC 32
#define OAL8b 4096u
#define OB8b  8192u
#define OBL8b 12288u

template<int MODE>
__global__ __launch_bounds__(GT, 2)
void gemm_cross_kernel()
{
    const uint8_t *A8 = g_xh8, *Al8 = g_xl8;
    const uint8_t *B8  = (MODE == 0) ? g_wkh8 : g_wvh8;
    const uint8_t *Bl8 = (MODE == 0) ? g_wkl8 : g_wvl8;
    const int Ktot = SIZE_K;

    extern __shared__ char smem[];
    const uint32_t sb = smem_u32(smem);
    const int tid  = threadIdx.x;
    const int wid  = tid >> 5;
    const int lane = tid & 31;
    const int wm   = wid & 3;
    const int wn   = wid >> 2;

    const int bm = blockIdx.x * BM;
    const int bn = blockIdx.y * BN;

    float acc[2][8][4];   // cross at 2^27 scale
    #pragma unroll
    for (int t = 0; t < 2; t++)
        #pragma unroll
        for (int n = 0; n < 8; n++)
            #pragma unroll
            for (int q = 0; q < 4; q++) acc[t][n][q] = 0.0f;

    const int nch = Ktot / B_BKC;

    auto load_chunk = [&](int ch) {
        const uint32_t stg = sb + (uint32_t)(ch % B_NSTG) * B_STG;
        const size_t k0 = (size_t)ch * B_BKC;
        int row = tid >> 1, c = tid & 1;
        uint32_t soff = row * 32 + ((c ^ ((row >> 2) & 1)) << 4);
        size_t ga = (size_t)(bm + row) * Ktot + k0 + c * 16;
        size_t gb = (size_t)(bn + row) * Ktot + k0 + c * 16;
        cp16(stg +         0 + soff, A8  + ga);
        cp16(stg + OAL8b     + soff, Al8 + ga);
        cp16(stg + OB8b      + soff, B8  + gb);
        cp16(stg + OBL8b     + soff, Bl8 + gb);
    };

    load_chunk(0); cp_commit();
    load_chunk(1); cp_commit();
    load_chunk(2); cp_commit();

    for (int ch = 0; ch < nch; ++ch) {
        cp_wait<2>();
        __syncthreads();
        if (ch + 3 < nch) load_chunk(ch + 3);
        cp_commit();

        const uint32_t stg = sb + (uint32_t)(ch % B_NSTG) * B_STG;

        uint32_t bh8[4][4], bl8[4][4];
        #pragma unroll
        for (int p = 0; p < 4; ++p) {
            int row = wn * 64 + p * 16 + ((lane >> 4) << 3) + (lane & 7);
            int kh  = (lane >> 3) & 1;
            uint32_t off = row * 32 + ((kh ^ ((row >> 2) & 1)) << 4);
            ldsm4(bh8[p], stg + OB8b  + off);
            ldsm4(bl8[p], stg + OBL8b + off);
        }
        #pragma unroll
        for (int t = 0; t < 2; ++t) {
            uint32_t ah8[4], al8[4];
            {
                int row = wm * 32 + t * 16 + (lane & 15);
                int kh  = lane >> 4;
                uint32_t off = row * 32 + ((kh ^ ((row >> 2) & 1)) << 4);
                ldsm4(ah8, stg + 0 + off);
                ldsm4(al8, stg + OAL8b + off);
            }
            #pragma unroll
            for (int nt = 0; nt < 8; ++nt)
                mma16832_e4m3(acc[t][nt], ah8, &bl8[nt >> 1][(nt & 1) * 2]);
            #pragma unroll
            for (int nt = 0; nt < 8; ++nt)
                mma16832_e4m3(acc[t][nt], al8, &bh8[nt >> 1][(nt & 1) * 2]);
        }
    }

    // epilogue: read hh partial, add cross, write fp32 (V only) + fp16 splits
    float* basef = (MODE == 0) ? g_k : g_v;
    __half* dsth = (MODE == 0) ? g_kh : g_vh;
    __half* dstl = (MODE == 0) ? g_kl : g_vl;
    #pragma unroll
    for (int t = 0; t < 2; ++t) {
        #pragma unroll
        for (int nt = 0; nt < 8; ++nt) {
            const int n  = bn + wn * 64 + nt * 8 + (lane & 3) * 2;
            const int m0 = bm + wm * 32 + t * 16 + (lane >> 2);
            float2 p0 = *(float2*)&basef[(size_t)m0 * HALF_K + n];
            float2 p1 = *(float2*)&basef[(size_t)(m0 + 8) * HALF_K + n];
            float x0 = p0.x + acc[t][nt][0] * INV_CROSS;
            float x1 = p0.y + acc[t][nt][1] * INV_CROSS;
            float y0 = p1.x + acc[t][nt][2] * INV_CROSS;
            float y1 = p1.y + acc[t][nt][3] * INV_CROSS;
            if (MODE == 1) {
                *(float2*)&basef[(size_t)m0 * HALF_K + n]       = make_float2(x0, x1);
                *(float2*)&basef[(size_t)(m0 + 8) * HALF_K + n] = make_float2(y0, y1);
            }
            uint32_t h, l;
            split2h(x0, x1, h, l);
            *(uint32_t*)&dsth[(size_t)m0 * HALF_K + n] = h;
            *(uint32_t*)&dstl[(size_t)m0 * HALF_K + n] = l;
            split2h(y0, y1, h, l);
            *(uint32_t*)&dsth[(size_t)(m0 + 8) * HALF_K + n] = h;
            *(uint32_t*)&dstl[(size_t)(m0 + 8) * HALF_K + n] = l;
        }
    }
}

// ---------------- scores GEMM: fp16 3-term, single fp32 acc (round-11) -------
#define S_STG 32768u
#define S_BUF 8192u
#define S_NSTG 3
#define S_SMEM (S_NSTG * S_STG)
#define S_BKC 32

__global__ __launch_bounds__(GT, 2)
void gemm_sc_kernel()
{
    const __half *Ah = g_vh, *Al = g_vl, *Bh = g_kh, *Bl = g_kl;
    const int Ktot = HALF_K;

    extern __shared__ char smem[];
    const uint32_t sb = smem_u32(smem);
    const int tid  = threadIdx.x;
    const int wid  = tid >> 5;
    const int lane = tid & 31;
    const int wm   = wid & 3;
    const int wn   = wid >> 2;

    const int bm = blockIdx.x * BM;
    const int bn = blockIdx.y * BN;

    float acc[2][8][4];
    #pragma unroll
    for (int t = 0; t < 2; t++)
        #pragma unroll
        for (int n = 0; n < 8; n++)
            #pragma unroll
            for (int q = 0; q < 4; q++) acc[t][n][q] = 0.0f;

    const int nch = Ktot / S_BKC;

    auto load_chunk = [&](int ch) {
        const uint32_t stg = sb + (uint32_t)(ch % S_NSTG) * S_STG;
        const size_t k0 = (size_t)ch * S_BKC;
        #pragma unroll
        for (int i = 0; i < 2; i++) {
            int pos = tid + i * GT;
            int row = pos >> 2, seg = pos & 3;
            uint32_t soff = row * 64 + ((seg ^ ((row >> 1) & 3)) << 4);
            size_t ga = (size_t)(bm + row) * Ktot + k0 + seg * 8;
            size_t gb = (size_t)(bn + row) * Ktot + k0 + seg * 8;
            cp16(stg +         0 + soff, Ah + ga);
            cp16(stg +     S_BUF + soff, Al + ga);
            cp16(stg + 2 * S_BUF + soff, Bh + gb);
            cp16(stg + 3 * S_BUF + soff, Bl + gb);
        }
    };

    load_chunk(0); cp_commit();
    load_chunk(1); cp_commit();

    for (int ch = 0; ch < nch; ++ch) {
        cp_wait<1>();
        __syncthreads();
        if (ch + 2 < nch) load_chunk(ch + 2);
        cp_commit();

        const uint32_t stg = sb + (uint32_t)(ch % S_NSTG) * S_STG;

        #pragma unroll
        for (int k16 = 0; k16 < 2; ++k16) {
            uint32_t afh[2][4], afl[2][4], bfh[4][4], bfl[4][4];
            #pragma unroll
            for (int t = 0; t < 2; ++t) {
                int row = wm * 32 + t * 16 + (lane & 15);
                int seg = k16 * 2 + (lane >> 4);
                uint32_t off = row * 64 + ((seg ^ ((row >> 1) & 3)) << 4);
                ldsm4(afh[t], stg + off);
                ldsm4(afl[t], stg + S_BUF + off);
            }
            #pragma unroll
            for (int p = 0; p < 4; ++p) {
                int row = wn * 64 + p * 16 + ((lane >> 4) << 3) + (lane & 7);
                int seg = k16 * 2 + ((lane >> 3) & 1);
                uint32_t off = row * 64 + ((seg ^ ((row >> 1) & 3)) << 4);
                ldsm4(bfh[p], stg + 2 * S_BUF + off);
                ldsm4(bfl[p], stg + 3 * S_BUF + off);
            }
            #pragma unroll
            for (int t = 0; t < 2; ++t)
                #pragma unroll
                for (int nt = 0; nt < 8; ++nt)
                    mma16816_f32(acc[t][nt], afh[t], &bfh[nt >> 1][(nt & 1) * 2]);
            #pragma unroll
            for (int t = 0; t < 2; ++t)
                #pragma unroll
                for (int nt = 0; nt < 8; ++nt)
                    mma16816_f32(acc[t][nt], afh[t], &bfl[nt >> 1][(nt & 1) * 2]);
            #pragma unroll
            for (int t = 0; t < 2; ++t)
                #pragma unroll
                for (int nt = 0; nt < 8; ++nt)
                    mma16816_f32(acc[t][nt], afl[t], &bfh[nt >> 1][(nt & 1) * 2]);
        }
    }

    #pragma unroll
    for (int t = 0; t < 2; ++t) {
        #pragma unroll
        for (int nt = 0; nt < 8; ++nt) {
            float* c = acc[t][nt];
            const int n  = bn + wn * 64 + nt * 8 + (lane & 3) * 2;
            const int m0 = bm + wm * 32 + t * 16 + (lane >> 2);
            const float a = 1.0f / 90.0f;
            *(float2*)&g_s[(size_t)m0 * N_SEQ + n]       = make_float2(c[0] * a, c[1] * a);
            *(float2*)&g_s[(size_t)(m0 + 8) * N_SEQ + n] = make_float2(c[2] * a, c[3] * a);
        }
    }
}

// ---------------- fast exp on the FMA pipe (no MUFU) -------------------------
__device__ __forceinline__ float fast_exp(float x) {
    x = fmaxf(x, -87.0f);
    const float L2E = 1.4426950408889634f;
    float t = x * L2E;
    float z = t + 12582912.0f;
    float n = z - 12582912.0f;
    float f = t - n;
    int   i = __float_as_int(z) - 0x4B400000;
    float p = 1.3333558146e-3f;
    p = fmaf(p, f, 9.6181291076e-3f);
    p = fmaf(p, f, 5.5504108665e-2f);
    p = fmaf(p, f, 2.4022650696e-1f);
    p = fmaf(p, f, 6.9314718056e-1f);
    p = fmaf(p, f, 1.0f);
    float sc = __int_as_float((i + 127) << 23);
    return p * sc;
}

__device__ __forceinline__ void combine(float& m, float& Z, float& c, int& bi,
                                        float m2, float Z2, float c2, int bi2) {
    float M  = fmaxf(m, m2);
    float r1 = fast_exp(m  - M);
    float r2 = fast_exp(m2 - M);
    Z = Z * r1 + Z2 * r2;
    float ca = c  * r1;
    float cb = c2 * r2;
    if (cb > ca || (cb == ca && bi2 < bi)) { c = cb; bi = bi2; }
    else                                   { c = ca; }
    m = M;
}

__global__ __launch_bounds__(256)
void softmax_combine_kernel(float* __restrict__ out)
{
    const int row = blockIdx.x;
    const float4* __restrict__ S4 = (const float4*)(g_s + (size_t)row * N_SEQ);
    const float4* __restrict__ V4 = (const float4*)(g_v + (size_t)row * N_SEQ);
    const int tid = threadIdx.x;

    float m = -INFINITY, Z = 0.0f, c = -INFINITY;
    int bi = 0;

    #pragma unroll
    for (int it = 0; it < 4; it++) {
        int q = tid + it * 256;
        float4 s4 = S4[q];
        float4 v4 = V4[q];
        float ss[4] = {s4.x, s4.y, s4.z, s4.w};
        float vv[4] = {v4.x, v4.y, v4.z, v4.w};
        #pragma unroll
        for (int l = 0; l < 4; l++) {
            float s = ss[l];
            int   j = q * 4 + l;
            if (s > m) {
                float r = fast_exp(m - s);
                Z = Z * r + 1.0f;
                c = c * r;
                float cand = vv[l];
                if (cand > c || (cand == c && j < bi)) { c = cand; bi = j; }
                m = s;
            } else {
                float e = fast_exp(s - m);
                Z += e;
                float cand = e * vv[l];
                if (cand > c || (cand == c && j < bi)) { c = cand; bi = j; }
            }
        }
    }

    const unsigned full = 0xffffffffu;
    #pragma unroll
    for (int off = 16; off > 0; off >>= 1) {
        float m2 = __shfl_down_sync(full, m, off);
        float Z2 = __shfl_down_sync(full, Z, off);
        float c2 = __shfl_down_sync(full, c, off);
        int   b2 = __shfl_down_sync(full, bi, off);
        combine(m, Z, c, bi, m2, Z2, c2, b2);
    }

    __shared__ float sm[8], sz[8], sc[8];
    __shared__ int   sbuf[8];
    int wid = tid >> 5, lane = tid & 31;
    if (lane == 0) { sm[wid] = m; sz[wid] = Z; sc[wid] = c; sbuf[wid] = bi; }
    __syncthreads();
    if (tid == 0) {
        #pragma unroll
        for (int w = 1; w < 8; w++)
            combine(m, Z, c, bi, sm[w], sz[w], sc[w], sbuf[w]);
        out[row]         = c / Z;
        out[N_SEQ + row] = (float)bi;
    }
}

// ---------------- launch ------------------------------------------------------
extern "C" void kernel_launch(void* const* d_in, const int* in_sizes, int n_in,
                              void* d_out, int out_size)
{
    const float* x  = (const float*)d_in[0];
    const float* Wk = (const float*)d_in[1];
    const float* bk = (const float*)d_in[2];
    const float* Wv = (const float*)d_in[3];
    const float* bv = (const float*)d_in[4];
    // d_in[5]/d_in[6] (Wq,bq) are dead in the reference (x_q = x@Wv+bv)
    float* out = (float*)d_out;

    static bool attr_done = false;
    if (!attr_done) {
        cudaFuncSetAttribute(gemm_hh_kernel<0>, cudaFuncAttributeMaxDynamicSharedMemorySize, A_SMEM);
        cudaFuncSetAttribute(gemm_hh_kernel<1>, cudaFuncAttributeMaxDynamicSharedMemorySize, A_SMEM);
        cudaFuncSetAttribute(gemm_cross_kernel<0>, cudaFuncAttributeMaxDynamicSharedMemorySize, B_SMEM);
        cudaFuncSetAttribute(gemm_cross_kernel<1>, cudaFuncAttributeMaxDynamicSharedMemorySize, B_SMEM);
        cudaFuncSetAttribute(gemm_sc_kernel, cudaFuncAttributeMaxDynamicSharedMemorySize, S_SMEM);
        attr_done = true;
    }

    // 1) split x into fp16 hi + fp8 hi/lo
    convert_x_kernel<<<8192, 256>>>(x);
    // 2) transpose+split weights (fp16 hi + fp8 hi/lo)
    dim3 tg(HALF_K / 32, SIZE_K / 32);
    transpose_split_kernel<0><<<tg, dim3(32, 8)>>>(Wk);
    transpose_split_kernel<1><<<tg, dim3(32, 8)>>>(Wv);
    // 3) projections: pass A (fp16 hh) then pass B (fp8 cross + split)
    dim3 gproj(N_SEQ / BM, HALF_K / BN);
    gemm_hh_kernel<0><<<gproj, GT, A_SMEM>>>(bk);
    gemm_cross_kernel<0><<<gproj, GT, B_SMEM>>>();
    gemm_hh_kernel<1><<<gproj, GT, A_SMEM>>>(bv);
    gemm_cross_kernel<1><<<gproj, GT, B_SMEM>>>();
    // 4) scores: fp16 3-term, single fp32 acc
    dim3 gsc(N_SEQ / BM, N_SEQ / BN);
    gemm_sc_kernel<<<gsc, GT, S_SMEM>>>();
    // 5) softmax + elementwise V + row max/argmax
    softmax_combine_kernel<<<N_SEQ, 256>>>(out);
}

// round 13
// speedup vs baseline: 1.2550x; 1.0731x over previous
#include <cuda_runtime.h>
#include <cuda_bf16.h>
#include <math.h>
#include <stdint.h>

#define N_SEQ  4096
#define SIZE_K 8192
#define HALF_K 4096
#define GT   256         // threads per GEMM CTA (8 warps)

// ---------------- scratch (static device globals; no runtime alloc) ----------
__device__ __nv_bfloat16 g_xh[(size_t)N_SEQ * SIZE_K];
__device__ __nv_bfloat16 g_xl[(size_t)N_SEQ * SIZE_K];
__device__ __nv_bfloat16 g_wkh[(size_t)HALF_K * SIZE_K];   // Wk^T hi  [4096,8192]
__device__ __nv_bfloat16 g_wkl[(size_t)HALF_K * SIZE_K];
__device__ __nv_bfloat16 g_wvh[(size_t)HALF_K * SIZE_K];
__device__ __nv_bfloat16 g_wvl[(size_t)HALF_K * SIZE_K];
__device__ __nv_bfloat16 g_kh[(size_t)N_SEQ * HALF_K];     // K split
__device__ __nv_bfloat16 g_kl[(size_t)N_SEQ * HALF_K];
__device__ __nv_bfloat16 g_vh[(size_t)N_SEQ * HALF_K];     // V split
__device__ __nv_bfloat16 g_vl[(size_t)N_SEQ * HALF_K];
__device__ float         g_v [(size_t)N_SEQ * HALF_K];     // V fp32
__device__ float         g_s [(size_t)N_SEQ * N_SEQ];      // scores fp32

// ---------------- PTX helpers (base sm_103 features only) --------------------
static __device__ __forceinline__ uint32_t smem_u32(const void* p) {
    uint32_t a;
    asm("{ .reg .u64 t; cvta.to.shared.u64 t, %1; cvt.u32.u64 %0, t; }" : "=r"(a) : "l"(p));
    return a;
}
static __device__ __forceinline__ void cp16(uint32_t s, const void* g) {
    asm volatile("cp.async.cg.shared.global [%0], [%1], 16;" :: "r"(s), "l"(g));
}
static __device__ __forceinline__ void cp_commit() {
    asm volatile("cp.async.commit_group;" ::: "memory");
}
template<int NP> static __device__ __forceinline__ void cp_wait() {
    asm volatile("cp.async.wait_group %0;" :: "n"(NP) : "memory");
}
static __device__ __forceinline__ void ldsm4(uint32_t* r, uint32_t addr) {
    asm volatile("ldmatrix.sync.aligned.m8n8.x4.shared.b16 {%0,%1,%2,%3}, [%4];"
        : "=r"(r[0]), "=r"(r[1]), "=r"(r[2]), "=r"(r[3]) : "r"(addr));
}
static __device__ __forceinline__ void mma16816(float* c, const uint32_t* a, const uint32_t* b) {
    asm volatile(
        "mma.sync.aligned.m16n8k16.row.col.f32.bf16.bf16.f32 "
        "{%0,%1,%2,%3}, {%4,%5,%6,%7}, {%8,%9}, {%0,%1,%2,%3};"
        : "+f"(c[0]), "+f"(c[1]), "+f"(c[2]), "+f"(c[3])
        : "r"(a[0]), "r"(a[1]), "r"(a[2]), "r"(a[3]), "r"(b[0]), "r"(b[1]));
}
static __device__ __forceinline__ void split2(float x0, float x1, uint32_t& h, uint32_t& l) {
    __nv_bfloat16 h0 = __float2bfloat16(x0), h1 = __float2bfloat16(x1);
    __nv_bfloat16 l0 = __float2bfloat16(x0 - __bfloat162float(h0));
    __nv_bfloat16 l1 = __float2bfloat16(x1 - __bfloat162float(h1));
    h = (uint32_t)__bfloat16_as_ushort(h0) | ((uint32_t)__bfloat16_as_ushort(h1) << 16);
    l = (uint32_t)__bfloat16_as_ushort(l0) | ((uint32_t)__bfloat16_as_ushort(l1) << 16);
}

// ---------------- convert / split kernels ------------------------------------
__global__ __launch_bounds__(256)
void convert_x_kernel(const float* __restrict__ x)
{
    const size_t total4 = (size_t)N_SEQ * SIZE_K / 4;
    __nv_bfloat162* xh2 = reinterpret_cast<__nv_bfloat162*>(g_xh);
    __nv_bfloat162* xl2 = reinterpret_cast<__nv_bfloat162*>(g_xl);
    for (size_t i = (size_t)blockIdx.x * blockDim.x + threadIdx.x; i < total4;
         i += (size_t)gridDim.x * blockDim.x) {
        float4 v = reinterpret_cast<const float4*>(x)[i];
        __nv_bfloat16 h0 = __float2bfloat16(v.x), h1 = __float2bfloat16(v.y);
        __nv_bfloat16 h2 = __float2bfloat16(v.z), h3 = __float2bfloat16(v.w);
        __nv_bfloat16 l0 = __float2bfloat16(v.x - __bfloat162float(h0));
        __nv_bfloat16 l1 = __float2bfloat16(v.y - __bfloat162float(h1));
        __nv_bfloat16 l2 = __float2bfloat16(v.z - __bfloat162float(h2));
        __nv_bfloat16 l3 = __float2bfloat16(v.w - __bfloat162float(h3));
        xh2[2 * i]     = __nv_bfloat162(h0, h1);
        xh2[2 * i + 1] = __nv_bfloat162(h2, h3);
        xl2[2 * i]     = __nv_bfloat162(l0, l1);
        xl2[2 * i + 1] = __nv_bfloat162(l2, l3);
    }
}

// W [SIZE_K, HALF_K] fp32 -> WT hi/lo [HALF_K, SIZE_K] bf16
template<int WSEL>
__global__ __launch_bounds__(256)
void transpose_split_kernel(const float* __restrict__ W)
{
    __nv_bfloat16* dh = (WSEL == 0) ? g_wkh : g_wvh;
    __nv_bfloat16* dl = (WSEL == 0) ? g_wkl : g_wvl;
    __shared__ float t[32][33];
    int n0 = blockIdx.x * 32;
    int k0 = blockIdx.y * 32;
    int tx = threadIdx.x, ty = threadIdx.y;   // block (32, 8)
    #pragma unroll
    for (int i = 0; i < 4; i++)
        t[ty + i * 8][tx] = W[(size_t)(k0 + ty + i * 8) * HALF_K + n0 + tx];
    __syncthreads();
    #pragma unroll
    for (int i = 0; i < 4; i++) {
        int n = n0 + ty + i * 8;
        int k = k0 + tx;
        float v = t[tx][ty + i * 8];
        __nv_bfloat16 h = __float2bfloat16(v);
        __nv_bfloat16 l = __float2bfloat16(v - __bfloat162float(h));
        dh[(size_t)n * SIZE_K + k] = h;
        dl[(size_t)n * SIZE_K + k] = l;
    }
}

// ---------------- projection GEMM: 128x256 CTA, warp 32x128, bf16 3-term -----
// MODE 0: K proj (out g_kh/g_kl, bias bk)  MODE 1: V proj (out g_v,g_vh/g_vl, bias bv)
// stage 48 KB (chunk K=32): Ah 8K | Al 8K | Bh 16K | Bl 16K. 3 stages.
#define PJ_BN  256
#define PJ_STG 49152u
#define PJ_NSTG 3
#define PJ_SMEM (PJ_NSTG * PJ_STG)
#define PJ_OAL 8192u
#define PJ_OBH 16384u
#define PJ_OBL 32768u
#define PJ_BKC 32

template<int MODE>
__global__ __launch_bounds__(GT, 1)
void gemm_proj_kernel(const float* __restrict__ bias)
{
    const __nv_bfloat16* Ah = g_xh;
    const __nv_bfloat16* Al = g_xl;
    const __nv_bfloat16* Bh = (MODE == 0) ? g_wkh : g_wvh;
    const __nv_bfloat16* Bl = (MODE == 0) ? g_wkl : g_wvl;
    const int Ktot = SIZE_K;

    extern __shared__ char smem[];
    const uint32_t sb = smem_u32(smem);
    const int tid  = threadIdx.x;
    const int wid  = tid >> 5;
    const int lane = tid & 31;
    const int wm   = wid & 3;     // warp row 0..3 (32 rows each)
    const int wn   = wid >> 2;    // warp col 0..1 (128 cols each)

    const int bm = blockIdx.x * 128;
    const int bn = blockIdx.y * PJ_BN;

    float acc[2][16][4];
    #pragma unroll
    for (int t = 0; t < 2; t++)
        #pragma unroll
        for (int n = 0; n < 16; n++)
            #pragma unroll
            for (int q = 0; q < 4; q++) acc[t][n][q] = 0.0f;

    const int nch = Ktot / PJ_BKC;

    auto load_chunk = [&](int ch) {
        const uint32_t stg = sb + (uint32_t)(ch % PJ_NSTG) * PJ_STG;
        const size_t k0 = (size_t)ch * PJ_BKC;
        // A tiles: 128 rows x 64B (hi + lo)
        #pragma unroll
        for (int i = 0; i < 2; i++) {
            int pos = tid + i * GT;            // 0..511
            int row = pos >> 2, seg = pos & 3;
            uint32_t soff = row * 64 + ((seg ^ ((row >> 1) & 3)) << 4);
            size_t ga = (size_t)(bm + row) * Ktot + k0 + seg * 8;
            cp16(stg +          soff, Ah + ga);
            cp16(stg + PJ_OAL + soff, Al + ga);
        }
        // B tiles: 256 rows x 64B (hi + lo)
        #pragma unroll
        for (int i = 0; i < 4; i++) {
            int pos = tid + i * GT;            // 0..1023
            int row = pos >> 2, seg = pos & 3;
            uint32_t soff = row * 64 + ((seg ^ ((row >> 1) & 3)) << 4);
            size_t gb = (size_t)(bn + row) * Ktot + k0 + seg * 8;
            cp16(stg + PJ_OBH + soff, Bh + gb);
            cp16(stg + PJ_OBL + soff, Bl + gb);
        }
    };

    load_chunk(0); cp_commit();
    load_chunk(1); cp_commit();

    for (int ch = 0; ch < nch; ++ch) {
        cp_wait<1>();
        __syncthreads();
        if (ch + 2 < nch) load_chunk(ch + 2);
        cp_commit();

        const uint32_t stg = sb + (uint32_t)(ch % PJ_NSTG) * PJ_STG;

        #pragma unroll
        for (int k16 = 0; k16 < 2; ++k16) {
            uint32_t afh[2][4], afl[2][4];
            #pragma unroll
            for (int t = 0; t < 2; ++t) {
                int row = wm * 32 + t * 16 + (lane & 15);
                int seg = k16 * 2 + (lane >> 4);
                uint32_t off = row * 64 + ((seg ^ ((row >> 1) & 3)) << 4);
                ldsm4(afh[t], stg + off);
                ldsm4(afl[t], stg + PJ_OAL + off);
            }
            #pragma unroll
            for (int p = 0; p < 8; ++p) {
                int row = wn * 128 + p * 16 + ((lane >> 4) << 3) + (lane & 7);
                int seg = k16 * 2 + ((lane >> 3) & 1);
                uint32_t off = row * 64 + ((seg ^ ((row >> 1) & 3)) << 4);
                uint32_t bh[4], bl[4];
                ldsm4(bh, stg + PJ_OBH + off);
                ldsm4(bl, stg + PJ_OBL + off);
                // hh
                #pragma unroll
                for (int t = 0; t < 2; ++t) {
                    mma16816(acc[t][2 * p],     afh[t], &bh[0]);
                    mma16816(acc[t][2 * p + 1], afh[t], &bh[2]);
                }
                // hl
                #pragma unroll
                for (int t = 0; t < 2; ++t) {
                    mma16816(acc[t][2 * p],     afh[t], &bl[0]);
                    mma16816(acc[t][2 * p + 1], afh[t], &bl[2]);
                }
                // lh
                #pragma unroll
                for (int t = 0; t < 2; ++t) {
                    mma16816(acc[t][2 * p],     afl[t], &bh[0]);
                    mma16816(acc[t][2 * p + 1], afl[t], &bh[2]);
                }
            }
        }
    }

    // ---- epilogue
    #pragma unroll
    for (int t = 0; t < 2; ++t) {
        #pragma unroll
        for (int nt = 0; nt < 16; ++nt) {
            float* c = acc[t][nt];
            const int n  = bn + wn * 128 + nt * 8 + (lane & 3) * 2;
            const int m0 = bm + wm * 32 + t * 16 + (lane >> 2);
            float b0 = __ldg(&bias[n]), b1 = __ldg(&bias[n + 1]);
            float x0 = c[0] + b0, x1 = c[1] + b1;
            float y0 = c[2] + b0, y1 = c[3] + b1;
            if (MODE == 1) {
                *(float2*)&g_v[(size_t)m0 * HALF_K + n]       = make_float2(x0, x1);
                *(float2*)&g_v[(size_t)(m0 + 8) * HALF_K + n] = make_float2(y0, y1);
            }
            __nv_bfloat16* dsth = (MODE == 0) ? g_kh : g_vh;
            __nv_bfloat16* dstl = (MODE == 0) ? g_kl : g_vl;
            uint32_t h, l;
            split2(x0, x1, h, l);
            *(uint32_t*)&dsth[(size_t)m0 * HALF_K + n] = h;
            *(uint32_t*)&dstl[(size_t)m0 * HALF_K + n] = l;
            split2(y0, y1, h, l);
            *(uint32_t*)&dsth[(size_t)(m0 + 8) * HALF_K + n] = h;
            *(uint32_t*)&dstl[(size_t)(m0 + 8) * HALF_K + n] = l;
        }
    }
}

// ---------------- scores GEMM: 128x128, bf16 3-term (round-5 proven) ---------
#define S_STG 32768u
#define S_BUF 8192u
#define S_NSTG 3
#define S_SMEM (S_NSTG * S_STG)
#define S_BKC 32

__global__ __launch_bounds__(GT, 2)
void gemm_sc_kernel()
{
    const __nv_bfloat16 *Ah = g_vh, *Al = g_vl, *Bh = g_kh, *Bl = g_kl;
    const int Ktot = HALF_K;

    extern __shared__ char smem[];
    const uint32_t sb = smem_u32(smem);
    const int tid  = threadIdx.x;
    const int wid  = tid >> 5;
    const int lane = tid & 31;
    const int wm   = wid & 3;
    const int wn   = wid >> 2;

    const int bm = blockIdx.x * 128;
    const int bn = blockIdx.y * 128;

    float acc[2][8][4];
    #pragma unroll
    for (int t = 0; t < 2; t++)
        #pragma unroll
        for (int n = 0; n < 8; n++)
            #pragma unroll
            for (int q = 0; q < 4; q++) acc[t][n][q] = 0.0f;

    const int nch = Ktot / S_BKC;

    auto load_chunk = [&](int ch) {
        const uint32_t stg = sb + (uint32_t)(ch % S_NSTG) * S_STG;
        const size_t k0 = (size_t)ch * S_BKC;
        #pragma unroll
        for (int i = 0; i < 2; i++) {
            int pos = tid + i * GT;
            int row = pos >> 2, seg = pos & 3;
            uint32_t soff = row * 64 + ((seg ^ ((row >> 1) & 3)) << 4);
            size_t ga = (size_t)(bm + row) * Ktot + k0 + seg * 8;
            size_t gb = (size_t)(bn + row) * Ktot + k0 + seg * 8;
            cp16(stg +         0 + soff, Ah + ga);
            cp16(stg +     S_BUF + soff, Al + ga);
            cp16(stg + 2 * S_BUF + soff, Bh + gb);
            cp16(stg + 3 * S_BUF + soff, Bl + gb);
        }
    };

    load_chunk(0); cp_commit();
    load_chunk(1); cp_commit();

    for (int ch = 0; ch < nch; ++ch) {
        cp_wait<1>();
        __syncthreads();
        if (ch + 2 < nch) load_chunk(ch + 2);
        cp_commit();

        const uint32_t stg = sb + (uint32_t)(ch % S_NSTG) * S_STG;

        #pragma unroll
        for (int k16 = 0; k16 < 2; ++k16) {
            uint32_t afh[2][4], afl[2][4], bfh[4][4], bfl[4][4];
            #pragma unroll
            for (int t = 0; t < 2; ++t) {
                int row = wm * 32 + t * 16 + (lane & 15);
                int seg = k16 * 2 + (lane >> 4);
                uint32_t off = row * 64 + ((seg ^ ((row >> 1) & 3)) << 4);
                ldsm4(afh[t], stg + off);
                ldsm4(afl[t], stg + S_BUF + off);
            }
            #pragma unroll
            for (int p = 0; p < 4; ++p) {
                int row = wn * 64 + p * 16 + ((lane >> 4) << 3) + (lane & 7);
                int seg = k16 * 2 + ((lane >> 3) & 1);
                uint32_t off = row * 64 + ((seg ^ ((row >> 1) & 3)) << 4);
                ldsm4(bfh[p], stg + 2 * S_BUF + off);
                ldsm4(bfl[p], stg + 3 * S_BUF + off);
            }
            #pragma unroll
            for (int t = 0; t < 2; ++t)
                #pragma unroll
                for (int nt = 0; nt < 8; ++nt)
                    mma16816(acc[t][nt], afh[t], &bfh[nt >> 1][(nt & 1) * 2]);
            #pragma unroll
            for (int t = 0; t < 2; ++t)
                #pragma unroll
                for (int nt = 0; nt < 8; ++nt)
                    mma16816(acc[t][nt], afh[t], &bfl[nt >> 1][(nt & 1) * 2]);
            #pragma unroll
            for (int t = 0; t < 2; ++t)
                #pragma unroll
                for (int nt = 0; nt < 8; ++nt)
                    mma16816(acc[t][nt], afl[t], &bfh[nt >> 1][(nt & 1) * 2]);
        }
    }

    #pragma unroll
    for (int t = 0; t < 2; ++t) {
        #pragma unroll
        for (int nt = 0; nt < 8; ++nt) {
            float* c = acc[t][nt];
            const int n  = bn + wn * 64 + nt * 8 + (lane & 3) * 2;
            const int m0 = bm + wm * 32 + t * 16 + (lane >> 2);
            const float a = 1.0f / 90.0f;
            *(float2*)&g_s[(size_t)m0 * N_SEQ + n]       = make_float2(c[0] * a, c[1] * a);
            *(float2*)&g_s[(size_t)(m0 + 8) * N_SEQ + n] = make_float2(c[2] * a, c[3] * a);
        }
    }
}

// ---------------- fast exp on the FMA pipe (no MUFU) -------------------------
__device__ __forceinline__ float fast_exp(float x) {
    x = fmaxf(x, -87.0f);
    const float L2E = 1.4426950408889634f;
    float t = x * L2E;
    float z = t + 12582912.0f;
    float n = z - 12582912.0f;
    float f = t - n;
    int   i = __float_as_int(z) - 0x4B400000;
    float p = 1.3333558146e-3f;
    p = fmaf(p, f, 9.6181291076e-3f);
    p = fmaf(p, f, 5.5504108665e-2f);
    p = fmaf(p, f, 2.4022650696e-1f);
    p = fmaf(p, f, 6.9314718056e-1f);
    p = fmaf(p, f, 1.0f);
    float sc = __int_as_float((i + 127) << 23);
    return p * sc;
}

__device__ __forceinline__ void combine(float& m, float& Z, float& c, int& bi,
                                        float m2, float Z2, float c2, int bi2) {
    float M  = fmaxf(m, m2);
    float r1 = fast_exp(m  - M);
    float r2 = fast_exp(m2 - M);
    Z = Z * r1 + Z2 * r2;
    float ca = c  * r1;
    float cb = c2 * r2;
    if (cb > ca || (cb == ca && bi2 < bi)) { c = cb; bi = bi2; }
    else                                   { c = ca; }
    m = M;
}

__global__ __launch_bounds__(256)
void softmax_combine_kernel(float* __restrict__ out)
{
    const int row = blockIdx.x;
    const float4* __restrict__ S4 = (const float4*)(g_s + (size_t)row * N_SEQ);
    const float4* __restrict__ V4 = (const float4*)(g_v + (size_t)row * N_SEQ);
    const int tid = threadIdx.x;

    float m = -INFINITY, Z = 0.0f, c = -INFINITY;
    int bi = 0;

    #pragma unroll
    for (int it = 0; it < 4; it++) {
        int q = tid + it * 256;
        float4 s4 = S4[q];
        float4 v4 = V4[q];
        float ss[4] = {s4.x, s4.y, s4.z, s4.w};
        float vv[4] = {v4.x, v4.y, v4.z, v4.w};
        #pragma unroll
        for (int l = 0; l < 4; l++) {
            float s = ss[l];
            int   j = q * 4 + l;
            if (s > m) {
                float r = fast_exp(m - s);
                Z = Z * r + 1.0f;
                c = c * r;
                float cand = vv[l];
                if (cand > c || (cand == c && j < bi)) { c = cand; bi = j; }
                m = s;
            } else {
                float e = fast_exp(s - m);
                Z += e;
                float cand = e * vv[l];
                if (cand > c || (cand == c && j < bi)) { c = cand; bi = j; }
            }
        }
    }

    const unsigned full = 0xffffffffu;
    #pragma unroll
    for (int off = 16; off > 0; off >>= 1) {
        float m2 = __shfl_down_sync(full, m, off);
        float Z2 = __shfl_down_sync(full, Z, off);
        float c2 = __shfl_down_sync(full, c, off);
        int   b2 = __shfl_down_sync(full, bi, off);
        combine(m, Z, c, bi, m2, Z2, c2, b2);
    }

    __shared__ float sm[8], sz[8], sc[8];
    __shared__ int   sbuf[8];
    int wid = tid >> 5, lane = tid & 31;
    if (lane == 0) { sm[wid] = m; sz[wid] = Z; sc[wid] = c; sbuf[wid] = bi; }
    __syncthreads();
    if (tid == 0) {
        #pragma unroll
        for (int w = 1; w < 8; w++)
            combine(m, Z, c, bi, sm[w], sz[w], sc[w], sbuf[w]);
        out[row]         = c / Z;
        out[N_SEQ + row] = (float)bi;
    }
}

// ---------------- launch ------------------------------------------------------
extern "C" void kernel_launch(void* const* d_in, const int* in_sizes, int n_in,
                              void* d_out, int out_size)
{
    const float* x  = (const float*)d_in[0];
    const float* Wk = (const float*)d_in[1];
    const float* bk = (const float*)d_in[2];
    const float* Wv = (const float*)d_in[3];
    const float* bv = (const float*)d_in[4];
    // d_in[5]/d_in[6] (Wq,bq) are dead in the reference (x_q = x@Wv+bv)
    float* out = (float*)d_out;

    static bool attr_done = false;
    if (!attr_done) {
        cudaFuncSetAttribute(gemm_proj_kernel<0>, cudaFuncAttributeMaxDynamicSharedMemorySize, PJ_SMEM);
        cudaFuncSetAttribute(gemm_proj_kernel<1>, cudaFuncAttributeMaxDynamicSharedMemorySize, PJ_SMEM);
        cudaFuncSetAttribute(gemm_sc_kernel, cudaFuncAttributeMaxDynamicSharedMemorySize, S_SMEM);
        attr_done = true;
    }

    // 1) split x into bf16 hi/lo
    convert_x_kernel<<<8192, 256>>>(x);
    // 2) transpose+split weights
    dim3 tg(HALF_K / 32, SIZE_K / 32);
    transpose_split_kernel<0><<<tg, dim3(32, 8)>>>(Wk);
    transpose_split_kernel<1><<<tg, dim3(32, 8)>>>(Wv);
    // 3) projections: 128x256 tiles, bf16 3-term
    dim3 gproj(N_SEQ / 128, HALF_K / PJ_BN);   // 32 x 16
    gemm_proj_kernel<0><<<gproj, GT, PJ_SMEM>>>(bk);
    gemm_proj_kernel<1><<<gproj, GT, PJ_SMEM>>>(bv);
    // 4) scores: 128x128 tiles, bf16 3-term
    dim3 gsc(N_SEQ / 128, N_SEQ / 128);        // 32 x 32
    gemm_sc_kernel<<<gsc, GT, S_SMEM>>>();
    // 5) softmax + elementwise V + row max/argmax
    softmax_combine_kernel<<<N_SEQ, 256>>>(out);
}